// round 3
// baseline (speedup 1.0000x reference)
#include <cuda_runtime.h>
#include <cuda_bf16.h>

#define S_LEN 2048
#define DM    1024
#define NH    16
#define DKH   64
#define BB    2

// scratch: [B,H,S,DK] layouts
__device__ float g_q[BB*NH*S_LEN*DKH];
__device__ float g_k[BB*NH*S_LEN*DKH];
__device__ float g_v[BB*NH*S_LEN*DKH];
__device__ float g_attn[BB*NH*S_LEN*DKH];

// ---------------------------------------------------------------------------
// QKV projection: out[b,h,s,dk] = X[b,s,:] @ W[n,:]^T + bias[n], n = h*64+dk
// 128x128 tile, BK=16, 256 threads, 8x8 micro-tile. grid.z selects Q/K/V.
// ---------------------------------------------------------------------------
__global__ __launch_bounds__(256) void qkv_proj_kernel(
    const float* __restrict__ xq, const float* __restrict__ xk, const float* __restrict__ xv,
    const float* __restrict__ Wq, const float* __restrict__ bq,
    const float* __restrict__ Wk, const float* __restrict__ bk,
    const float* __restrict__ Wv, const float* __restrict__ bv)
{
    int z = blockIdx.z;
    const float* X    = (z == 0) ? xq : (z == 1) ? xk : xv;
    const float* W    = (z == 0) ? Wq : (z == 1) ? Wk : Wv;
    const float* bias = (z == 0) ? bq : (z == 1) ? bk : bv;
    float* out        = (z == 0) ? g_q : (z == 1) ? g_k : g_v;

    __shared__ __align__(16) float As[16][132];   // [k][m], pad 132
    __shared__ __align__(16) float Bs[16][132];   // [k][n]

    int tid = threadIdx.x;
    int m0 = blockIdx.y * 128;
    int n0 = blockIdx.x * 128;
    int ty = tid >> 4, tx = tid & 15;
    int lrow = tid >> 1;           // 0..127
    int lc0  = (tid & 1) * 8;      // 0 or 8

    const float* Abase = X + (size_t)(m0 + lrow) * DM + lc0;
    const float* Bbase = W + (size_t)(n0 + lrow) * DM + lc0;

    float4 a0 = *(const float4*)(Abase + 0);
    float4 a1 = *(const float4*)(Abase + 4);
    float4 b0 = *(const float4*)(Bbase + 0);
    float4 b1 = *(const float4*)(Bbase + 4);

    float acc[8][8] = {};

    for (int k0 = 0; k0 < DM; k0 += 16) {
        __syncthreads();
        As[lc0 + 0][lrow] = a0.x; As[lc0 + 1][lrow] = a0.y;
        As[lc0 + 2][lrow] = a0.z; As[lc0 + 3][lrow] = a0.w;
        As[lc0 + 4][lrow] = a1.x; As[lc0 + 5][lrow] = a1.y;
        As[lc0 + 6][lrow] = a1.z; As[lc0 + 7][lrow] = a1.w;
        Bs[lc0 + 0][lrow] = b0.x; Bs[lc0 + 1][lrow] = b0.y;
        Bs[lc0 + 2][lrow] = b0.z; Bs[lc0 + 3][lrow] = b0.w;
        Bs[lc0 + 4][lrow] = b1.x; Bs[lc0 + 5][lrow] = b1.y;
        Bs[lc0 + 6][lrow] = b1.z; Bs[lc0 + 7][lrow] = b1.w;
        __syncthreads();
        if (k0 + 16 < DM) {
            a0 = *(const float4*)(Abase + k0 + 16);
            a1 = *(const float4*)(Abase + k0 + 20);
            b0 = *(const float4*)(Bbase + k0 + 16);
            b1 = *(const float4*)(Bbase + k0 + 20);
        }
        #pragma unroll
        for (int kk = 0; kk < 16; kk++) {
            float4 av0 = *(const float4*)&As[kk][ty * 8];
            float4 av1 = *(const float4*)&As[kk][ty * 8 + 4];
            float4 bv0 = *(const float4*)&Bs[kk][tx * 8];
            float4 bv1 = *(const float4*)&Bs[kk][tx * 8 + 4];
            float av[8] = {av0.x, av0.y, av0.z, av0.w, av1.x, av1.y, av1.z, av1.w};
            float bvv[8] = {bv0.x, bv0.y, bv0.z, bv0.w, bv1.x, bv1.y, bv1.z, bv1.w};
            #pragma unroll
            for (int i = 0; i < 8; i++)
                #pragma unroll
                for (int j = 0; j < 8; j++)
                    acc[i][j] += av[i] * bvv[j];
        }
    }

    // epilogue: bias + scatter to [B,H,S,DK]
    int nbase = n0 + tx * 8;           // 8 consecutive cols, within one head
    int h = nbase >> 6, dk = nbase & 63;
    float bj[8];
    #pragma unroll
    for (int j = 0; j < 8; j++) bj[j] = bias[nbase + j];

    #pragma unroll
    for (int i = 0; i < 8; i++) {
        int m = m0 + ty * 8 + i;
        int b_ = m >> 11, s = m & 2047;
        float* op = out + (((size_t)(b_ * NH + h)) * S_LEN + s) * DKH + dk;
        float4 r0 = make_float4(acc[i][0] + bj[0], acc[i][1] + bj[1],
                                acc[i][2] + bj[2], acc[i][3] + bj[3]);
        float4 r1 = make_float4(acc[i][4] + bj[4], acc[i][5] + bj[5],
                                acc[i][6] + bj[6], acc[i][7] + bj[7]);
        *(float4*)(op + 0) = r0;
        *(float4*)(op + 4) = r1;
    }
}

// ---------------------------------------------------------------------------
// Flash attention: block = (64 q rows, one (b,h)). kv tiles of 64.
// 128 threads: rg = tid>>4 (0..7) owns 8 rows, cg = tid&15 owns 4 cols.
// Smem: Qt [d][r] 16KB, KP (Kt [d][k], reused as P [r][k]) 16KB, Vs [k][d] 16KB.
// ---------------------------------------------------------------------------
__global__ __launch_bounds__(128) void attn_kernel(const int* __restrict__ mask)
{
    __shared__ __align__(16) float Qt[64][64];   // [d][r]
    __shared__ __align__(16) float KP[64][64];   // Kt: [d][k]; reused as P: [r][k]
    __shared__ __align__(16) float Vs[64][64];   // [k][d]

    int tid = threadIdx.x;
    int bh = blockIdx.y;
    int b  = bh >> 4;
    int q0 = blockIdx.x * 64;
    int rg = tid >> 4;     // 0..7
    int cg = tid & 15;     // 0..15

    const float* Qg = g_q + (size_t)bh * S_LEN * DKH;
    const float* Kg = g_k + (size_t)bh * S_LEN * DKH;
    const float* Vg = g_v + (size_t)bh * S_LEN * DKH;

    // load Q tile transposed: row = tid>>1 (0..63), c0 = (tid&1)*32
    {
        int row = tid >> 1;
        int c0 = (tid & 1) * 32;
        #pragma unroll
        for (int c = 0; c < 32; c += 4) {
            float4 v = *(const float4*)&Qg[(size_t)(q0 + row) * DKH + c0 + c];
            Qt[c0 + c + 0][row] = v.x; Qt[c0 + c + 1][row] = v.y;
            Qt[c0 + c + 2][row] = v.z; Qt[c0 + c + 3][row] = v.w;
        }
    }

    float m_i[8], l_i[8];
    #pragma unroll
    for (int i = 0; i < 8; i++) { m_i[i] = -1e30f; l_i[i] = 0.f; }
    float o[8][4] = {};

    for (int k0 = 0; k0 < S_LEN; k0 += 64) {
        __syncthreads();   // prior iteration's PV reads of KP/Vs done
        {
            int row = tid >> 1;
            int c0 = (tid & 1) * 32;
            #pragma unroll
            for (int c = 0; c < 32; c += 4) {
                float4 kv = *(const float4*)&Kg[(size_t)(k0 + row) * DKH + c0 + c];
                KP[c0 + c + 0][row] = kv.x; KP[c0 + c + 1][row] = kv.y;
                KP[c0 + c + 2][row] = kv.z; KP[c0 + c + 3][row] = kv.w;
                float4 vv = *(const float4*)&Vg[(size_t)(k0 + row) * DKH + c0 + c];
                *(float4*)&Vs[row][c0 + c] = vv;
            }
        }
        __syncthreads();

        // S = Q K^T (8x4 per thread)
        float s[8][4] = {};
        #pragma unroll 8
        for (int d = 0; d < 64; d++) {
            float4 av0 = *(const float4*)&Qt[d][rg * 8];
            float4 av1 = *(const float4*)&Qt[d][rg * 8 + 4];
            float4 b4  = *(const float4*)&KP[d][cg * 4];
            float av[8] = {av0.x, av0.y, av0.z, av0.w, av1.x, av1.y, av1.z, av1.w};
            float bv[4] = {b4.x, b4.y, b4.z, b4.w};
            #pragma unroll
            for (int i = 0; i < 8; i++)
                #pragma unroll
                for (int j = 0; j < 4; j++)
                    s[i][j] += av[i] * bv[j];
        }

        // scale + mask (scores/8; masked -> -1e9, exactly as reference)
        const int* mbase = mask + ((size_t)b * S_LEN + q0 + rg * 8) * S_LEN + k0 + cg * 4;
        #pragma unroll
        for (int i = 0; i < 8; i++) {
            int4 mv = *(const int4*)(mbase + (size_t)i * S_LEN);
            s[i][0] = mv.x ? s[i][0] * 0.125f : -1e9f;
            s[i][1] = mv.y ? s[i][1] * 0.125f : -1e9f;
            s[i][2] = mv.z ? s[i][2] * 0.125f : -1e9f;
            s[i][3] = mv.w ? s[i][3] * 0.125f : -1e9f;
        }

        // online softmax per row; row group = 16 consecutive lanes
        #pragma unroll
        for (int i = 0; i < 8; i++) {
            float mx = fmaxf(fmaxf(s[i][0], s[i][1]), fmaxf(s[i][2], s[i][3]));
            #pragma unroll
            for (int off = 1; off < 16; off <<= 1)
                mx = fmaxf(mx, __shfl_xor_sync(0xffffffffu, mx, off));
            float mnew  = fmaxf(m_i[i], mx);
            float alpha = __expf(m_i[i] - mnew);
            m_i[i] = mnew;
            float ls = 0.f;
            #pragma unroll
            for (int j = 0; j < 4; j++) { s[i][j] = __expf(s[i][j] - mnew); ls += s[i][j]; }
            #pragma unroll
            for (int off = 1; off < 16; off <<= 1)
                ls += __shfl_xor_sync(0xffffffffu, ls, off);
            l_i[i] = l_i[i] * alpha + ls;
            #pragma unroll
            for (int j = 0; j < 4; j++) o[i][j] *= alpha;
        }

        __syncthreads();   // everyone done reading Kt before reuse as P
        // store P in natural orientation [r][k], vectorized (conflict-free)
        #pragma unroll
        for (int i = 0; i < 8; i++)
            *(float4*)&KP[rg * 8 + i][cg * 4] = make_float4(s[i][0], s[i][1], s[i][2], s[i][3]);
        __syncwarp();      // P row exchange is intra-half-warp (16-lane row groups)

        // O += P @ V, reading P as float4 along k
        #pragma unroll 4
        for (int k4 = 0; k4 < 64; k4 += 4) {
            float4 v0 = *(const float4*)&Vs[k4 + 0][cg * 4];
            float4 v1 = *(const float4*)&Vs[k4 + 1][cg * 4];
            float4 v2 = *(const float4*)&Vs[k4 + 2][cg * 4];
            float4 v3 = *(const float4*)&Vs[k4 + 3][cg * 4];
            #pragma unroll
            for (int i = 0; i < 8; i++) {
                float4 p = *(const float4*)&KP[rg * 8 + i][k4];
                o[i][0] += p.x * v0.x + p.y * v1.x + p.z * v2.x + p.w * v3.x;
                o[i][1] += p.x * v0.y + p.y * v1.y + p.z * v2.y + p.w * v3.y;
                o[i][2] += p.x * v0.z + p.y * v1.z + p.z * v2.z + p.w * v3.z;
                o[i][3] += p.x * v0.w + p.y * v1.w + p.z * v2.w + p.w * v3.w;
            }
        }
    }

    #pragma unroll
    for (int i = 0; i < 8; i++) {
        float inv = 1.0f / l_i[i];
        float4 r4 = make_float4(o[i][0] * inv, o[i][1] * inv, o[i][2] * inv, o[i][3] * inv);
        *(float4*)&g_attn[((size_t)bh * S_LEN + q0 + rg * 8 + i) * DKH + cg * 4] = r4;
    }
}

// ---------------------------------------------------------------------------
// Output projection: out[b,s,n] = attn[b,s,:] (head-gathered) @ Wo[n,:]^T + bo
// 128x128 tile, BK=16, 256 threads, 8x8 micro-tile.
// ---------------------------------------------------------------------------
__global__ __launch_bounds__(256) void out_proj_kernel(
    const float* __restrict__ Wo, const float* __restrict__ bo, float* __restrict__ out)
{
    __shared__ __align__(16) float As[16][132];
    __shared__ __align__(16) float Bs[16][132];

    int tid = threadIdx.x;
    int m0 = blockIdx.y * 128;
    int n0 = blockIdx.x * 128;
    int ty = tid >> 4, tx = tid & 15;
    int lrow = tid >> 1;
    int lc0  = (tid & 1) * 8;

    int m  = m0 + lrow;
    int b_ = m >> 11, ss = m & 2047;
    const float* arow = g_attn + ((size_t)b_ * NH) * S_LEN * DKH + (size_t)ss * DKH;
    // element k of logical row: arow[(k>>6)*S_LEN*DKH + (k&63)]
    const float* Bbase = Wo + (size_t)(n0 + lrow) * DM + lc0;

    auto lda = [&](int k) -> float4 {
        return *(const float4*)(arow + (size_t)(k >> 6) * (S_LEN * DKH) + (k & 63));
    };

    float4 a0 = lda(lc0);
    float4 a1 = lda(lc0 + 4);
    float4 b0 = *(const float4*)(Bbase + 0);
    float4 b1 = *(const float4*)(Bbase + 4);

    float acc[8][8] = {};

    for (int k0 = 0; k0 < DM; k0 += 16) {
        __syncthreads();
        As[lc0 + 0][lrow] = a0.x; As[lc0 + 1][lrow] = a0.y;
        As[lc0 + 2][lrow] = a0.z; As[lc0 + 3][lrow] = a0.w;
        As[lc0 + 4][lrow] = a1.x; As[lc0 + 5][lrow] = a1.y;
        As[lc0 + 6][lrow] = a1.z; As[lc0 + 7][lrow] = a1.w;
        Bs[lc0 + 0][lrow] = b0.x; Bs[lc0 + 1][lrow] = b0.y;
        Bs[lc0 + 2][lrow] = b0.z; Bs[lc0 + 3][lrow] = b0.w;
        Bs[lc0 + 4][lrow] = b1.x; Bs[lc0 + 5][lrow] = b1.y;
        Bs[lc0 + 6][lrow] = b1.z; Bs[lc0 + 7][lrow] = b1.w;
        __syncthreads();
        if (k0 + 16 < DM) {
            a0 = lda(k0 + 16 + lc0);
            a1 = lda(k0 + 20 + lc0);
            b0 = *(const float4*)(Bbase + k0 + 16);
            b1 = *(const float4*)(Bbase + k0 + 20);
        }
        #pragma unroll
        for (int kk = 0; kk < 16; kk++) {
            float4 av0 = *(const float4*)&As[kk][ty * 8];
            float4 av1 = *(const float4*)&As[kk][ty * 8 + 4];
            float4 bv0 = *(const float4*)&Bs[kk][tx * 8];
            float4 bv1 = *(const float4*)&Bs[kk][tx * 8 + 4];
            float av[8] = {av0.x, av0.y, av0.z, av0.w, av1.x, av1.y, av1.z, av1.w};
            float bvv[8] = {bv0.x, bv0.y, bv0.z, bv0.w, bv1.x, bv1.y, bv1.z, bv1.w};
            #pragma unroll
            for (int i = 0; i < 8; i++)
                #pragma unroll
                for (int j = 0; j < 8; j++)
                    acc[i][j] += av[i] * bvv[j];
        }
    }

    int nbase = n0 + tx * 8;
    float bj[8];
    #pragma unroll
    for (int j = 0; j < 8; j++) bj[j] = bo[nbase + j];

    #pragma unroll
    for (int i = 0; i < 8; i++) {
        size_t mrow = (size_t)(m0 + ty * 8 + i) * DM;
        float4 r0 = make_float4(acc[i][0] + bj[0], acc[i][1] + bj[1],
                                acc[i][2] + bj[2], acc[i][3] + bj[3]);
        float4 r1 = make_float4(acc[i][4] + bj[4], acc[i][5] + bj[5],
                                acc[i][6] + bj[6], acc[i][7] + bj[7]);
        *(float4*)(out + mrow + nbase + 0) = r0;
        *(float4*)(out + mrow + nbase + 4) = r1;
    }
}

extern "C" void kernel_launch(void* const* d_in, const int* in_sizes, int n_in,
                              void* d_out, int out_size)
{
    const float* query = (const float*)d_in[0];
    const float* key_  = (const float*)d_in[1];
    const float* value = (const float*)d_in[2];
    const int*   mask  = (const int*)d_in[3];
    const float* Wq = (const float*)d_in[4];
    const float* bq = (const float*)d_in[5];
    const float* Wk = (const float*)d_in[6];
    const float* bk = (const float*)d_in[7];
    const float* Wv = (const float*)d_in[8];
    const float* bv = (const float*)d_in[9];
    const float* Wo = (const float*)d_in[10];
    const float* bo = (const float*)d_in[11];
    float* out = (float*)d_out;

    dim3 g1(DM / 128, (BB * S_LEN) / 128, 3);
    qkv_proj_kernel<<<g1, 256>>>(query, key_, value, Wq, bq, Wk, bk, Wv, bv);

    dim3 g2(S_LEN / 64, BB * NH);
    attn_kernel<<<g2, 128>>>(mask);

    dim3 g3(DM / 128, (BB * S_LEN) / 128);
    out_proj_kernel<<<g3, 256>>>(Wo, bo, out);
}

// round 4
// speedup vs baseline: 1.0012x; 1.0012x over previous
#include <cuda_runtime.h>
#include <cuda_bf16.h>

#define S_LEN 2048
#define DM    1024
#define NH    16
#define DKH   64
#define BB    2

// scratch: [B,H,S,DK] layouts
__device__ float g_q[BB*NH*S_LEN*DKH];
__device__ float g_k[BB*NH*S_LEN*DKH];
__device__ float g_v[BB*NH*S_LEN*DKH];
__device__ float g_attn[BB*NH*S_LEN*DKH];

// ---------------------------------------------------------------------------
// QKV projection: out[b,h,s,dk] = X[b,s,:] @ W[n,:]^T + bias[n], n = h*64+dk
// 128x128 tile, BK=16, 256 threads, 8x8 micro-tile. grid.z selects Q/K/V.
// ---------------------------------------------------------------------------
__global__ __launch_bounds__(256) void qkv_proj_kernel(
    const float* __restrict__ xq, const float* __restrict__ xk, const float* __restrict__ xv,
    const float* __restrict__ Wq, const float* __restrict__ bq,
    const float* __restrict__ Wk, const float* __restrict__ bk,
    const float* __restrict__ Wv, const float* __restrict__ bv)
{
    int z = blockIdx.z;
    const float* X    = (z == 0) ? xq : (z == 1) ? xk : xv;
    const float* W    = (z == 0) ? Wq : (z == 1) ? Wk : Wv;
    const float* bias = (z == 0) ? bq : (z == 1) ? bk : bv;
    float* out        = (z == 0) ? g_q : (z == 1) ? g_k : g_v;

    __shared__ __align__(16) float As[16][132];   // [k][m], pad 132
    __shared__ __align__(16) float Bs[16][132];   // [k][n]

    int tid = threadIdx.x;
    int m0 = blockIdx.y * 128;
    int n0 = blockIdx.x * 128;
    int ty = tid >> 4, tx = tid & 15;
    int lrow = tid >> 1;           // 0..127
    int lc0  = (tid & 1) * 8;      // 0 or 8

    const float* Abase = X + (size_t)(m0 + lrow) * DM + lc0;
    const float* Bbase = W + (size_t)(n0 + lrow) * DM + lc0;

    float4 a0 = *(const float4*)(Abase + 0);
    float4 a1 = *(const float4*)(Abase + 4);
    float4 b0 = *(const float4*)(Bbase + 0);
    float4 b1 = *(const float4*)(Bbase + 4);

    float acc[8][8] = {};

    for (int k0 = 0; k0 < DM; k0 += 16) {
        __syncthreads();
        As[lc0 + 0][lrow] = a0.x; As[lc0 + 1][lrow] = a0.y;
        As[lc0 + 2][lrow] = a0.z; As[lc0 + 3][lrow] = a0.w;
        As[lc0 + 4][lrow] = a1.x; As[lc0 + 5][lrow] = a1.y;
        As[lc0 + 6][lrow] = a1.z; As[lc0 + 7][lrow] = a1.w;
        Bs[lc0 + 0][lrow] = b0.x; Bs[lc0 + 1][lrow] = b0.y;
        Bs[lc0 + 2][lrow] = b0.z; Bs[lc0 + 3][lrow] = b0.w;
        Bs[lc0 + 4][lrow] = b1.x; Bs[lc0 + 5][lrow] = b1.y;
        Bs[lc0 + 6][lrow] = b1.z; Bs[lc0 + 7][lrow] = b1.w;
        __syncthreads();
        if (k0 + 16 < DM) {
            a0 = *(const float4*)(Abase + k0 + 16);
            a1 = *(const float4*)(Abase + k0 + 20);
            b0 = *(const float4*)(Bbase + k0 + 16);
            b1 = *(const float4*)(Bbase + k0 + 20);
        }
        #pragma unroll
        for (int kk = 0; kk < 16; kk++) {
            float4 av0 = *(const float4*)&As[kk][ty * 8];
            float4 av1 = *(const float4*)&As[kk][ty * 8 + 4];
            float4 bv0 = *(const float4*)&Bs[kk][tx * 8];
            float4 bv1 = *(const float4*)&Bs[kk][tx * 8 + 4];
            float av[8] = {av0.x, av0.y, av0.z, av0.w, av1.x, av1.y, av1.z, av1.w};
            float bvv[8] = {bv0.x, bv0.y, bv0.z, bv0.w, bv1.x, bv1.y, bv1.z, bv1.w};
            #pragma unroll
            for (int i = 0; i < 8; i++)
                #pragma unroll
                for (int j = 0; j < 8; j++)
                    acc[i][j] += av[i] * bvv[j];
        }
    }

    // epilogue: bias + scatter to [B,H,S,DK]
    int nbase = n0 + tx * 8;           // 8 consecutive cols, within one head
    int h = nbase >> 6, dk = nbase & 63;
    float bj[8];
    #pragma unroll
    for (int j = 0; j < 8; j++) bj[j] = bias[nbase + j];

    #pragma unroll
    for (int i = 0; i < 8; i++) {
        int m = m0 + ty * 8 + i;
        int b_ = m >> 11, s = m & 2047;
        float* op = out + (((size_t)(b_ * NH + h)) * S_LEN + s) * DKH + dk;
        float4 r0 = make_float4(acc[i][0] + bj[0], acc[i][1] + bj[1],
                                acc[i][2] + bj[2], acc[i][3] + bj[3]);
        float4 r1 = make_float4(acc[i][4] + bj[4], acc[i][5] + bj[5],
                                acc[i][6] + bj[6], acc[i][7] + bj[7]);
        *(float4*)(op + 0) = r0;
        *(float4*)(op + 4) = r1;
    }
}

// ---------------------------------------------------------------------------
// Flash attention: block = (64 q rows, one (b,h)). kv tiles of 64.
// 128 threads: rg = tid>>4 (0..7) owns 8 rows, cg = tid&15 owns 4 cols.
// Smem: Qt [d][r] 16KB, KP (Kt [d][k], reused as P [r][k]) 16KB, Vs [k][d] 16KB.
// ---------------------------------------------------------------------------
__global__ __launch_bounds__(128) void attn_kernel(const int* __restrict__ mask)
{
    __shared__ __align__(16) float Qt[64][64];   // [d][r]
    __shared__ __align__(16) float KP[64][64];   // Kt: [d][k]; reused as P: [r][k]
    __shared__ __align__(16) float Vs[64][64];   // [k][d]

    int tid = threadIdx.x;
    int bh = blockIdx.y;
    int b  = bh >> 4;
    int q0 = blockIdx.x * 64;
    int rg = tid >> 4;     // 0..7
    int cg = tid & 15;     // 0..15

    const float* Qg = g_q + (size_t)bh * S_LEN * DKH;
    const float* Kg = g_k + (size_t)bh * S_LEN * DKH;
    const float* Vg = g_v + (size_t)bh * S_LEN * DKH;

    // load Q tile transposed: row = tid>>1 (0..63), c0 = (tid&1)*32
    {
        int row = tid >> 1;
        int c0 = (tid & 1) * 32;
        #pragma unroll
        for (int c = 0; c < 32; c += 4) {
            float4 v = *(const float4*)&Qg[(size_t)(q0 + row) * DKH + c0 + c];
            Qt[c0 + c + 0][row] = v.x; Qt[c0 + c + 1][row] = v.y;
            Qt[c0 + c + 2][row] = v.z; Qt[c0 + c + 3][row] = v.w;
        }
    }

    float m_i[8], l_i[8];
    #pragma unroll
    for (int i = 0; i < 8; i++) { m_i[i] = -1e30f; l_i[i] = 0.f; }
    float o[8][4] = {};

    for (int k0 = 0; k0 < S_LEN; k0 += 64) {
        __syncthreads();   // prior iteration's PV reads of KP/Vs done
        {
            int row = tid >> 1;
            int c0 = (tid & 1) * 32;
            #pragma unroll
            for (int c = 0; c < 32; c += 4) {
                float4 kv = *(const float4*)&Kg[(size_t)(k0 + row) * DKH + c0 + c];
                KP[c0 + c + 0][row] = kv.x; KP[c0 + c + 1][row] = kv.y;
                KP[c0 + c + 2][row] = kv.z; KP[c0 + c + 3][row] = kv.w;
                float4 vv = *(const float4*)&Vg[(size_t)(k0 + row) * DKH + c0 + c];
                *(float4*)&Vs[row][c0 + c] = vv;
            }
        }
        __syncthreads();

        // S = Q K^T (8x4 per thread)
        float s[8][4] = {};
        #pragma unroll 8
        for (int d = 0; d < 64; d++) {
            float4 av0 = *(const float4*)&Qt[d][rg * 8];
            float4 av1 = *(const float4*)&Qt[d][rg * 8 + 4];
            float4 b4  = *(const float4*)&KP[d][cg * 4];
            float av[8] = {av0.x, av0.y, av0.z, av0.w, av1.x, av1.y, av1.z, av1.w};
            float bv[4] = {b4.x, b4.y, b4.z, b4.w};
            #pragma unroll
            for (int i = 0; i < 8; i++)
                #pragma unroll
                for (int j = 0; j < 4; j++)
                    s[i][j] += av[i] * bv[j];
        }

        // scale + mask (scores/8; masked -> -1e9, exactly as reference)
        const int* mbase = mask + ((size_t)b * S_LEN + q0 + rg * 8) * S_LEN + k0 + cg * 4;
        #pragma unroll
        for (int i = 0; i < 8; i++) {
            int4 mv = *(const int4*)(mbase + (size_t)i * S_LEN);
            s[i][0] = mv.x ? s[i][0] * 0.125f : -1e9f;
            s[i][1] = mv.y ? s[i][1] * 0.125f : -1e9f;
            s[i][2] = mv.z ? s[i][2] * 0.125f : -1e9f;
            s[i][3] = mv.w ? s[i][3] * 0.125f : -1e9f;
        }

        // online softmax per row; row group = 16 consecutive lanes
        #pragma unroll
        for (int i = 0; i < 8; i++) {
            float mx = fmaxf(fmaxf(s[i][0], s[i][1]), fmaxf(s[i][2], s[i][3]));
            #pragma unroll
            for (int off = 1; off < 16; off <<= 1)
                mx = fmaxf(mx, __shfl_xor_sync(0xffffffffu, mx, off));
            float mnew  = fmaxf(m_i[i], mx);
            float alpha = __expf(m_i[i] - mnew);
            m_i[i] = mnew;
            float ls = 0.f;
            #pragma unroll
            for (int j = 0; j < 4; j++) { s[i][j] = __expf(s[i][j] - mnew); ls += s[i][j]; }
            #pragma unroll
            for (int off = 1; off < 16; off <<= 1)
                ls += __shfl_xor_sync(0xffffffffu, ls, off);
            l_i[i] = l_i[i] * alpha + ls;
            #pragma unroll
            for (int j = 0; j < 4; j++) o[i][j] *= alpha;
        }

        __syncthreads();   // everyone done reading Kt before reuse as P
        // store P in natural orientation [r][k], vectorized (conflict-free)
        #pragma unroll
        for (int i = 0; i < 8; i++)
            *(float4*)&KP[rg * 8 + i][cg * 4] = make_float4(s[i][0], s[i][1], s[i][2], s[i][3]);
        __syncwarp();      // P row exchange is intra-half-warp (16-lane row groups)

        // O += P @ V, reading P as float4 along k
        #pragma unroll 4
        for (int k4 = 0; k4 < 64; k4 += 4) {
            float4 v0 = *(const float4*)&Vs[k4 + 0][cg * 4];
            float4 v1 = *(const float4*)&Vs[k4 + 1][cg * 4];
            float4 v2 = *(const float4*)&Vs[k4 + 2][cg * 4];
            float4 v3 = *(const float4*)&Vs[k4 + 3][cg * 4];
            #pragma unroll
            for (int i = 0; i < 8; i++) {
                float4 p = *(const float4*)&KP[rg * 8 + i][k4];
                o[i][0] += p.x * v0.x + p.y * v1.x + p.z * v2.x + p.w * v3.x;
                o[i][1] += p.x * v0.y + p.y * v1.y + p.z * v2.y + p.w * v3.y;
                o[i][2] += p.x * v0.z + p.y * v1.z + p.z * v2.z + p.w * v3.z;
                o[i][3] += p.x * v0.w + p.y * v1.w + p.z * v2.w + p.w * v3.w;
            }
        }
    }

    #pragma unroll
    for (int i = 0; i < 8; i++) {
        float inv = 1.0f / l_i[i];
        float4 r4 = make_float4(o[i][0] * inv, o[i][1] * inv, o[i][2] * inv, o[i][3] * inv);
        *(float4*)&g_attn[((size_t)bh * S_LEN + q0 + rg * 8 + i) * DKH + cg * 4] = r4;
    }
}

// ---------------------------------------------------------------------------
// Output projection: out[b,s,n] = attn[b,s,:] (head-gathered) @ Wo[n,:]^T + bo
// 128x128 tile, BK=16, 256 threads, 8x8 micro-tile.
// ---------------------------------------------------------------------------
__global__ __launch_bounds__(256) void out_proj_kernel(
    const float* __restrict__ Wo, const float* __restrict__ bo, float* __restrict__ out)
{
    __shared__ __align__(16) float As[16][132];
    __shared__ __align__(16) float Bs[16][132];

    int tid = threadIdx.x;
    int m0 = blockIdx.y * 128;
    int n0 = blockIdx.x * 128;
    int ty = tid >> 4, tx = tid & 15;
    int lrow = tid >> 1;
    int lc0  = (tid & 1) * 8;

    int m  = m0 + lrow;
    int b_ = m >> 11, ss = m & 2047;
    const float* arow = g_attn + ((size_t)b_ * NH) * S_LEN * DKH + (size_t)ss * DKH;
    // element k of logical row: arow[(k>>6)*S_LEN*DKH + (k&63)]
    const float* Bbase = Wo + (size_t)(n0 + lrow) * DM + lc0;

    auto lda = [&](int k) -> float4 {
        return *(const float4*)(arow + (size_t)(k >> 6) * (S_LEN * DKH) + (k & 63));
    };

    float4 a0 = lda(lc0);
    float4 a1 = lda(lc0 + 4);
    float4 b0 = *(const float4*)(Bbase + 0);
    float4 b1 = *(const float4*)(Bbase + 4);

    float acc[8][8] = {};

    for (int k0 = 0; k0 < DM; k0 += 16) {
        __syncthreads();
        As[lc0 + 0][lrow] = a0.x; As[lc0 + 1][lrow] = a0.y;
        As[lc0 + 2][lrow] = a0.z; As[lc0 + 3][lrow] = a0.w;
        As[lc0 + 4][lrow] = a1.x; As[lc0 + 5][lrow] = a1.y;
        As[lc0 + 6][lrow] = a1.z; As[lc0 + 7][lrow] = a1.w;
        Bs[lc0 + 0][lrow] = b0.x; Bs[lc0 + 1][lrow] = b0.y;
        Bs[lc0 + 2][lrow] = b0.z; Bs[lc0 + 3][lrow] = b0.w;
        Bs[lc0 + 4][lrow] = b1.x; Bs[lc0 + 5][lrow] = b1.y;
        Bs[lc0 + 6][lrow] = b1.z; Bs[lc0 + 7][lrow] = b1.w;
        __syncthreads();
        if (k0 + 16 < DM) {
            a0 = lda(k0 + 16 + lc0);
            a1 = lda(k0 + 20 + lc0);
            b0 = *(const float4*)(Bbase + k0 + 16);
            b1 = *(const float4*)(Bbase + k0 + 20);
        }
        #pragma unroll
        for (int kk = 0; kk < 16; kk++) {
            float4 av0 = *(const float4*)&As[kk][ty * 8];
            float4 av1 = *(const float4*)&As[kk][ty * 8 + 4];
            float4 bv0 = *(const float4*)&Bs[kk][tx * 8];
            float4 bv1 = *(const float4*)&Bs[kk][tx * 8 + 4];
            float av[8] = {av0.x, av0.y, av0.z, av0.w, av1.x, av1.y, av1.z, av1.w};
            float bvv[8] = {bv0.x, bv0.y, bv0.z, bv0.w, bv1.x, bv1.y, bv1.z, bv1.w};
            #pragma unroll
            for (int i = 0; i < 8; i++)
                #pragma unroll
                for (int j = 0; j < 8; j++)
                    acc[i][j] += av[i] * bvv[j];
        }
    }

    int nbase = n0 + tx * 8;
    float bj[8];
    #pragma unroll
    for (int j = 0; j < 8; j++) bj[j] = bo[nbase + j];

    #pragma unroll
    for (int i = 0; i < 8; i++) {
        size_t mrow = (size_t)(m0 + ty * 8 + i) * DM;
        float4 r0 = make_float4(acc[i][0] + bj[0], acc[i][1] + bj[1],
                                acc[i][2] + bj[2], acc[i][3] + bj[3]);
        float4 r1 = make_float4(acc[i][4] + bj[4], acc[i][5] + bj[5],
                                acc[i][6] + bj[6], acc[i][7] + bj[7]);
        *(float4*)(out + mrow + nbase + 0) = r0;
        *(float4*)(out + mrow + nbase + 4) = r1;
    }
}

extern "C" void kernel_launch(void* const* d_in, const int* in_sizes, int n_in,
                              void* d_out, int out_size)
{
    const float* query = (const float*)d_in[0];
    const float* key_  = (const float*)d_in[1];
    const float* value = (const float*)d_in[2];
    const int*   mask  = (const int*)d_in[3];
    const float* Wq = (const float*)d_in[4];
    const float* bq = (const float*)d_in[5];
    const float* Wk = (const float*)d_in[6];
    const float* bk = (const float*)d_in[7];
    const float* Wv = (const float*)d_in[8];
    const float* bv = (const float*)d_in[9];
    const float* Wo = (const float*)d_in[10];
    const float* bo = (const float*)d_in[11];
    float* out = (float*)d_out;

    dim3 g1(DM / 128, (BB * S_LEN) / 128, 3);
    qkv_proj_kernel<<<g1, 256>>>(query, key_, value, Wq, bq, Wk, bk, Wv, bv);

    dim3 g2(S_LEN / 64, BB * NH);
    attn_kernel<<<g2, 128>>>(mask);

    dim3 g3(DM / 128, (BB * S_LEN) / 128);
    out_proj_kernel<<<g3, 256>>>(Wo, bo, out);
}

// round 5
// speedup vs baseline: 1.3509x; 1.3492x over previous
#include <cuda_runtime.h>
#include <cuda_bf16.h>
#include <cstdint>

#define S_LEN 2048
#define DM    1024
#define NH    16
#define DKH   64
#define BB    2

// scratch: [B,H,S,DK] layouts
__device__ float g_q[BB*NH*S_LEN*DKH];
__device__ float g_k[BB*NH*S_LEN*DKH];
__device__ float g_v[BB*NH*S_LEN*DKH];
__device__ float g_attn[BB*NH*S_LEN*DKH];

// ---------------------------------------------------------------------------
// MMA helpers (sm_80+ warp-level, bf16 in / f32 out)
// ---------------------------------------------------------------------------
__device__ __forceinline__ void ldsm_x4(uint32_t& r0, uint32_t& r1, uint32_t& r2, uint32_t& r3,
                                        uint32_t addr) {
    asm volatile("ldmatrix.sync.aligned.m8n8.x4.shared.b16 {%0,%1,%2,%3}, [%4];"
                 : "=r"(r0), "=r"(r1), "=r"(r2), "=r"(r3) : "r"(addr));
}

__device__ __forceinline__ void mma_bf16(float* c, const uint32_t* a, const uint32_t* b) {
    asm volatile(
        "mma.sync.aligned.m16n8k16.row.col.f32.bf16.bf16.f32 "
        "{%0,%1,%2,%3}, {%4,%5,%6,%7}, {%8,%9}, {%0,%1,%2,%3};"
        : "+f"(c[0]), "+f"(c[1]), "+f"(c[2]), "+f"(c[3])
        : "r"(a[0]), "r"(a[1]), "r"(a[2]), "r"(a[3]), "r"(b[0]), "r"(b[1]));
}

// split 8 floats into bf16 hi/lo and store 16B each
__device__ __forceinline__ void split_store(float4 u0, float4 u1,
                                            __nv_bfloat16* dst_hi, __nv_bfloat16* dst_lo) {
    float x[8] = {u0.x, u0.y, u0.z, u0.w, u1.x, u1.y, u1.z, u1.w};
    __nv_bfloat162 h[4], l[4];
    #pragma unroll
    for (int i = 0; i < 4; i++) {
        float a = x[2*i], b = x[2*i+1];
        __nv_bfloat16 ha = __float2bfloat16_rn(a);
        __nv_bfloat16 hb = __float2bfloat16_rn(b);
        __nv_bfloat16 la = __float2bfloat16_rn(a - __bfloat162float(ha));
        __nv_bfloat16 lb = __float2bfloat16_rn(b - __bfloat162float(hb));
        h[i] = __nv_bfloat162(ha, hb);
        l[i] = __nv_bfloat162(la, lb);
    }
    *(uint4*)dst_hi = *(uint4*)h;
    *(uint4*)dst_lo = *(uint4*)l;
}

// smem layout constants for the GEMM kernels
#define LDAB 24            // bf16 elements per row (16 data + 8 pad -> 48B, conflict-free LDSM)
#define T_A_HI 0
#define T_A_LO (128*LDAB)
#define T_B_HI (2*128*LDAB)
#define T_B_LO (3*128*LDAB)

// ---------------------------------------------------------------------------
// QKV projection: out[b,h,s,dk] = X[b,s,:] @ W[n,:]^T + bias[n], n = h*64+dk
// 128x128 tile, BK=16, 256 threads (8 warps, 2m x 4n), warp tile 64x32.
// bf16-split tensor-core GEMM (hh + hl + lh), fp32 accumulate.
// ---------------------------------------------------------------------------
__global__ __launch_bounds__(256) void qkv_proj_kernel(
    const float* __restrict__ xq, const float* __restrict__ xk, const float* __restrict__ xv,
    const float* __restrict__ Wq, const float* __restrict__ bq,
    const float* __restrict__ Wk, const float* __restrict__ bk,
    const float* __restrict__ Wv, const float* __restrict__ bv)
{
    int z = blockIdx.z;
    const float* X    = (z == 0) ? xq : (z == 1) ? xk : xv;
    const float* W    = (z == 0) ? Wq : (z == 1) ? Wk : Wv;
    const float* bias = (z == 0) ? bq : (z == 1) ? bk : bv;
    float* out        = (z == 0) ? g_q : (z == 1) ? g_k : g_v;

    __shared__ __align__(16) __nv_bfloat16 sm[4*128*LDAB];   // 24 KB

    int tid  = threadIdx.x;
    int lane = tid & 31;
    int wid  = tid >> 5;
    int wm   = wid & 1;        // 0..1  -> m offset wm*64
    int wn   = wid >> 1;       // 0..3  -> n offset wn*32
    int m0 = blockIdx.y * 128;
    int n0 = blockIdx.x * 128;

    // global load mapping: each thread owns one row, 8 k
    int grow = tid >> 1;               // 0..127
    int gk8  = (tid & 1) * 8;          // 0 or 8
    const float* Abase = X + (size_t)(m0 + grow) * DM + gk8;
    const float* Bbase = W + (size_t)(n0 + grow) * DM + gk8;
    __nv_bfloat16* sa_hi = sm + T_A_HI + grow * LDAB + gk8;
    __nv_bfloat16* sa_lo = sm + T_A_LO + grow * LDAB + gk8;
    __nv_bfloat16* sb_hi = sm + T_B_HI + grow * LDAB + gk8;
    __nv_bfloat16* sb_lo = sm + T_B_LO + grow * LDAB + gk8;

    // ldmatrix addresses (per lane, fixed)
    uint32_t smem_u32 = (uint32_t)__cvta_generic_to_shared(sm);
    int a_row = lane & 15, a_kh = (lane >> 4) * 8;
    uint32_t adA[4], adAlo[4];
    #pragma unroll
    for (int mt = 0; mt < 4; mt++) {
        int r = wm * 64 + mt * 16 + a_row;
        adA[mt]   = smem_u32 + (uint32_t)(T_A_HI + r * LDAB + a_kh) * 2;
        adAlo[mt] = smem_u32 + (uint32_t)(T_A_LO + r * LDAB + a_kh) * 2;
    }
    int b_nrow = ((lane >> 4) & 1) * 8 + (lane & 7);
    int b_k    = ((lane >> 3) & 1) * 8;
    uint32_t adB[2], adBlo[2];
    #pragma unroll
    for (int p = 0; p < 2; p++) {
        int r = wn * 32 + p * 16 + b_nrow;
        adB[p]   = smem_u32 + (uint32_t)(T_B_HI + r * LDAB + b_k) * 2;
        adBlo[p] = smem_u32 + (uint32_t)(T_B_LO + r * LDAB + b_k) * 2;
    }

    float C[4][4][4] = {};     // [mt][nt][frag]

    float4 a0 = *(const float4*)(Abase + 0);
    float4 a1 = *(const float4*)(Abase + 4);
    float4 b0 = *(const float4*)(Bbase + 0);
    float4 b1 = *(const float4*)(Bbase + 4);

    for (int k0 = 0; k0 < DM; k0 += 16) {
        __syncthreads();
        split_store(a0, a1, sa_hi, sa_lo);
        split_store(b0, b1, sb_hi, sb_lo);
        __syncthreads();
        if (k0 + 16 < DM) {
            a0 = *(const float4*)(Abase + k0 + 16);
            a1 = *(const float4*)(Abase + k0 + 20);
            b0 = *(const float4*)(Bbase + k0 + 16);
            b1 = *(const float4*)(Bbase + k0 + 20);
        }

        uint32_t A[4][4], Bh[4][2], Bl[4][2];
        #pragma unroll
        for (int mt = 0; mt < 4; mt++)
            ldsm_x4(A[mt][0], A[mt][1], A[mt][2], A[mt][3], adA[mt]);
        #pragma unroll
        for (int p = 0; p < 2; p++) {
            uint32_t r0, r1, r2, r3;
            ldsm_x4(r0, r1, r2, r3, adB[p]);
            Bh[p*2+0][0] = r0; Bh[p*2+0][1] = r1;
            Bh[p*2+1][0] = r2; Bh[p*2+1][1] = r3;
            ldsm_x4(r0, r1, r2, r3, adBlo[p]);
            Bl[p*2+0][0] = r0; Bl[p*2+0][1] = r1;
            Bl[p*2+1][0] = r2; Bl[p*2+1][1] = r3;
        }
        // hh + hl
        #pragma unroll
        for (int mt = 0; mt < 4; mt++)
            #pragma unroll
            for (int nt = 0; nt < 4; nt++) {
                mma_bf16(C[mt][nt], A[mt], Bh[nt]);
                mma_bf16(C[mt][nt], A[mt], Bl[nt]);
            }
        // lh: reload A as lo
        #pragma unroll
        for (int mt = 0; mt < 4; mt++)
            ldsm_x4(A[mt][0], A[mt][1], A[mt][2], A[mt][3], adAlo[mt]);
        #pragma unroll
        for (int mt = 0; mt < 4; mt++)
            #pragma unroll
            for (int nt = 0; nt < 4; nt++)
                mma_bf16(C[mt][nt], A[mt], Bh[nt]);
    }

    // epilogue: bias + scatter to [B,H,S,DK]
    int crow = lane >> 2;
    int ccol = (lane & 3) * 2;
    #pragma unroll
    for (int nt = 0; nt < 4; nt++) {
        int n = n0 + wn * 32 + nt * 8 + ccol;
        int h = n >> 6, dk = n & 63;
        float bi0 = bias[n], bi1 = bias[n + 1];
        #pragma unroll
        for (int mt = 0; mt < 4; mt++) {
            #pragma unroll
            for (int half = 0; half < 2; half++) {
                int m = m0 + wm * 64 + mt * 16 + crow + half * 8;
                int b_ = m >> 11, s = m & 2047;
                float* op = out + (((size_t)(b_ * NH + h)) * S_LEN + s) * DKH + dk;
                float2 r = make_float2(C[mt][nt][half*2+0] + bi0, C[mt][nt][half*2+1] + bi1);
                *(float2*)op = r;
            }
        }
    }
}

// ---------------------------------------------------------------------------
// Output projection: out[b,s,n] = attn[b,s,:] (head-gathered) @ Wo[n,:]^T + bo
// Same bf16-split MMA structure as qkv_proj.
// ---------------------------------------------------------------------------
__global__ __launch_bounds__(256) void out_proj_kernel(
    const float* __restrict__ Wo, const float* __restrict__ bo, float* __restrict__ out)
{
    __shared__ __align__(16) __nv_bfloat16 sm[4*128*LDAB];

    int tid  = threadIdx.x;
    int lane = tid & 31;
    int wid  = tid >> 5;
    int wm   = wid & 1;
    int wn   = wid >> 1;
    int m0 = blockIdx.y * 128;
    int n0 = blockIdx.x * 128;

    int grow = tid >> 1;
    int gk8  = (tid & 1) * 8;
    int m  = m0 + grow;
    int b_ = m >> 11, ss = m & 2047;
    const float* arow = g_attn + ((size_t)b_ * NH) * S_LEN * DKH + (size_t)ss * DKH;
    const float* Bbase = Wo + (size_t)(n0 + grow) * DM + gk8;
    __nv_bfloat16* sa_hi = sm + T_A_HI + grow * LDAB + gk8;
    __nv_bfloat16* sa_lo = sm + T_A_LO + grow * LDAB + gk8;
    __nv_bfloat16* sb_hi = sm + T_B_HI + grow * LDAB + gk8;
    __nv_bfloat16* sb_lo = sm + T_B_LO + grow * LDAB + gk8;

    auto lda = [&](int k) -> float4 {
        return *(const float4*)(arow + (size_t)(k >> 6) * (S_LEN * DKH) + (k & 63));
    };

    uint32_t smem_u32 = (uint32_t)__cvta_generic_to_shared(sm);
    int a_row = lane & 15, a_kh = (lane >> 4) * 8;
    uint32_t adA[4], adAlo[4];
    #pragma unroll
    for (int mt = 0; mt < 4; mt++) {
        int r = wm * 64 + mt * 16 + a_row;
        adA[mt]   = smem_u32 + (uint32_t)(T_A_HI + r * LDAB + a_kh) * 2;
        adAlo[mt] = smem_u32 + (uint32_t)(T_A_LO + r * LDAB + a_kh) * 2;
    }
    int b_nrow = ((lane >> 4) & 1) * 8 + (lane & 7);
    int b_k    = ((lane >> 3) & 1) * 8;
    uint32_t adB[2], adBlo[2];
    #pragma unroll
    for (int p = 0; p < 2; p++) {
        int r = wn * 32 + p * 16 + b_nrow;
        adB[p]   = smem_u32 + (uint32_t)(T_B_HI + r * LDAB + b_k) * 2;
        adBlo[p] = smem_u32 + (uint32_t)(T_B_LO + r * LDAB + b_k) * 2;
    }

    float C[4][4][4] = {};

    float4 a0 = lda(gk8);
    float4 a1 = lda(gk8 + 4);
    float4 b0 = *(const float4*)(Bbase + 0);
    float4 b1 = *(const float4*)(Bbase + 4);

    for (int k0 = 0; k0 < DM; k0 += 16) {
        __syncthreads();
        split_store(a0, a1, sa_hi, sa_lo);
        split_store(b0, b1, sb_hi, sb_lo);
        __syncthreads();
        if (k0 + 16 < DM) {
            a0 = lda(k0 + 16 + gk8);
            a1 = lda(k0 + 16 + gk8 + 4);
            b0 = *(const float4*)(Bbase + k0 + 16);
            b1 = *(const float4*)(Bbase + k0 + 20);
        }

        uint32_t A[4][4], Bh[4][2], Bl[4][2];
        #pragma unroll
        for (int mt = 0; mt < 4; mt++)
            ldsm_x4(A[mt][0], A[mt][1], A[mt][2], A[mt][3], adA[mt]);
        #pragma unroll
        for (int p = 0; p < 2; p++) {
            uint32_t r0, r1, r2, r3;
            ldsm_x4(r0, r1, r2, r3, adB[p]);
            Bh[p*2+0][0] = r0; Bh[p*2+0][1] = r1;
            Bh[p*2+1][0] = r2; Bh[p*2+1][1] = r3;
            ldsm_x4(r0, r1, r2, r3, adBlo[p]);
            Bl[p*2+0][0] = r0; Bl[p*2+0][1] = r1;
            Bl[p*2+1][0] = r2; Bl[p*2+1][1] = r3;
        }
        #pragma unroll
        for (int mt = 0; mt < 4; mt++)
            #pragma unroll
            for (int nt = 0; nt < 4; nt++) {
                mma_bf16(C[mt][nt], A[mt], Bh[nt]);
                mma_bf16(C[mt][nt], A[mt], Bl[nt]);
            }
        #pragma unroll
        for (int mt = 0; mt < 4; mt++)
            ldsm_x4(A[mt][0], A[mt][1], A[mt][2], A[mt][3], adAlo[mt]);
        #pragma unroll
        for (int mt = 0; mt < 4; mt++)
            #pragma unroll
            for (int nt = 0; nt < 4; nt++)
                mma_bf16(C[mt][nt], A[mt], Bh[nt]);
    }

    int crow = lane >> 2;
    int ccol = (lane & 3) * 2;
    #pragma unroll
    for (int nt = 0; nt < 4; nt++) {
        int n = n0 + wn * 32 + nt * 8 + ccol;
        float bi0 = bo[n], bi1 = bo[n + 1];
        #pragma unroll
        for (int mt = 0; mt < 4; mt++) {
            #pragma unroll
            for (int half = 0; half < 2; half++) {
                int mr = m0 + wm * 64 + mt * 16 + crow + half * 8;
                float2 r = make_float2(C[mt][nt][half*2+0] + bi0, C[mt][nt][half*2+1] + bi1);
                *(float2*)(out + (size_t)mr * DM + n) = r;
            }
        }
    }
}

// ---------------------------------------------------------------------------
// Flash attention: unchanged scalar fp32 (R4) — tensorization next round.
// ---------------------------------------------------------------------------
__global__ __launch_bounds__(128) void attn_kernel(const int* __restrict__ mask)
{
    __shared__ __align__(16) float Qt[64][64];   // [d][r]
    __shared__ __align__(16) float KP[64][64];   // Kt: [d][k]; reused as P: [r][k]
    __shared__ __align__(16) float Vs[64][64];   // [k][d]

    int tid = threadIdx.x;
    int bh = blockIdx.y;
    int b  = bh >> 4;
    int q0 = blockIdx.x * 64;
    int rg = tid >> 4;     // 0..7
    int cg = tid & 15;     // 0..15

    const float* Qg = g_q + (size_t)bh * S_LEN * DKH;
    const float* Kg = g_k + (size_t)bh * S_LEN * DKH;
    const float* Vg = g_v + (size_t)bh * S_LEN * DKH;

    {
        int row = tid >> 1;
        int c0 = (tid & 1) * 32;
        #pragma unroll
        for (int c = 0; c < 32; c += 4) {
            float4 v = *(const float4*)&Qg[(size_t)(q0 + row) * DKH + c0 + c];
            Qt[c0 + c + 0][row] = v.x; Qt[c0 + c + 1][row] = v.y;
            Qt[c0 + c + 2][row] = v.z; Qt[c0 + c + 3][row] = v.w;
        }
    }

    float m_i[8], l_i[8];
    #pragma unroll
    for (int i = 0; i < 8; i++) { m_i[i] = -1e30f; l_i[i] = 0.f; }
    float o[8][4] = {};

    for (int k0 = 0; k0 < S_LEN; k0 += 64) {
        __syncthreads();
        {
            int row = tid >> 1;
            int c0 = (tid & 1) * 32;
            #pragma unroll
            for (int c = 0; c < 32; c += 4) {
                float4 kv = *(const float4*)&Kg[(size_t)(k0 + row) * DKH + c0 + c];
                KP[c0 + c + 0][row] = kv.x; KP[c0 + c + 1][row] = kv.y;
                KP[c0 + c + 2][row] = kv.z; KP[c0 + c + 3][row] = kv.w;
                float4 vv = *(const float4*)&Vg[(size_t)(k0 + row) * DKH + c0 + c];
                *(float4*)&Vs[row][c0 + c] = vv;
            }
        }
        __syncthreads();

        float s[8][4] = {};
        #pragma unroll 8
        for (int d = 0; d < 64; d++) {
            float4 av0 = *(const float4*)&Qt[d][rg * 8];
            float4 av1 = *(const float4*)&Qt[d][rg * 8 + 4];
            float4 b4  = *(const float4*)&KP[d][cg * 4];
            float av[8] = {av0.x, av0.y, av0.z, av0.w, av1.x, av1.y, av1.z, av1.w};
            float bv[4] = {b4.x, b4.y, b4.z, b4.w};
            #pragma unroll
            for (int i = 0; i < 8; i++)
                #pragma unroll
                for (int j = 0; j < 4; j++)
                    s[i][j] += av[i] * bv[j];
        }

        const int* mbase = mask + ((size_t)b * S_LEN + q0 + rg * 8) * S_LEN + k0 + cg * 4;
        #pragma unroll
        for (int i = 0; i < 8; i++) {
            int4 mv = *(const int4*)(mbase + (size_t)i * S_LEN);
            s[i][0] = mv.x ? s[i][0] * 0.125f : -1e9f;
            s[i][1] = mv.y ? s[i][1] * 0.125f : -1e9f;
            s[i][2] = mv.z ? s[i][2] * 0.125f : -1e9f;
            s[i][3] = mv.w ? s[i][3] * 0.125f : -1e9f;
        }

        #pragma unroll
        for (int i = 0; i < 8; i++) {
            float mx = fmaxf(fmaxf(s[i][0], s[i][1]), fmaxf(s[i][2], s[i][3]));
            #pragma unroll
            for (int off = 1; off < 16; off <<= 1)
                mx = fmaxf(mx, __shfl_xor_sync(0xffffffffu, mx, off));
            float mnew  = fmaxf(m_i[i], mx);
            float alpha = __expf(m_i[i] - mnew);
            m_i[i] = mnew;
            float ls = 0.f;
            #pragma unroll
            for (int j = 0; j < 4; j++) { s[i][j] = __expf(s[i][j] - mnew); ls += s[i][j]; }
            #pragma unroll
            for (int off = 1; off < 16; off <<= 1)
                ls += __shfl_xor_sync(0xffffffffu, ls, off);
            l_i[i] = l_i[i] * alpha + ls;
            #pragma unroll
            for (int j = 0; j < 4; j++) o[i][j] *= alpha;
        }

        __syncthreads();
        #pragma unroll
        for (int i = 0; i < 8; i++)
            *(float4*)&KP[rg * 8 + i][cg * 4] = make_float4(s[i][0], s[i][1], s[i][2], s[i][3]);
        __syncwarp();

        #pragma unroll 4
        for (int k4 = 0; k4 < 64; k4 += 4) {
            float4 v0 = *(const float4*)&Vs[k4 + 0][cg * 4];
            float4 v1 = *(const float4*)&Vs[k4 + 1][cg * 4];
            float4 v2 = *(const float4*)&Vs[k4 + 2][cg * 4];
            float4 v3 = *(const float4*)&Vs[k4 + 3][cg * 4];
            #pragma unroll
            for (int i = 0; i < 8; i++) {
                float4 p = *(const float4*)&KP[rg * 8 + i][k4];
                o[i][0] += p.x * v0.x + p.y * v1.x + p.z * v2.x + p.w * v3.x;
                o[i][1] += p.x * v0.y + p.y * v1.y + p.z * v2.y + p.w * v3.y;
                o[i][2] += p.x * v0.z + p.y * v1.z + p.z * v2.z + p.w * v3.z;
                o[i][3] += p.x * v0.w + p.y * v1.w + p.z * v2.w + p.w * v3.w;
            }
        }
    }

    #pragma unroll
    for (int i = 0; i < 8; i++) {
        float inv = 1.0f / l_i[i];
        float4 r4 = make_float4(o[i][0] * inv, o[i][1] * inv, o[i][2] * inv, o[i][3] * inv);
        *(float4*)&g_attn[((size_t)bh * S_LEN + q0 + rg * 8 + i) * DKH + cg * 4] = r4;
    }
}

extern "C" void kernel_launch(void* const* d_in, const int* in_sizes, int n_in,
                              void* d_out, int out_size)
{
    const float* query = (const float*)d_in[0];
    const float* key_  = (const float*)d_in[1];
    const float* value = (const float*)d_in[2];
    const int*   mask  = (const int*)d_in[3];
    const float* Wq = (const float*)d_in[4];
    const float* bq = (const float*)d_in[5];
    const float* Wk = (const float*)d_in[6];
    const float* bk = (const float*)d_in[7];
    const float* Wv = (const float*)d_in[8];
    const float* bv = (const float*)d_in[9];
    const float* Wo = (const float*)d_in[10];
    const float* bo = (const float*)d_in[11];
    float* out = (float*)d_out;

    dim3 g1(DM / 128, (BB * S_LEN) / 128, 3);
    qkv_proj_kernel<<<g1, 256>>>(query, key_, value, Wq, bq, Wk, bk, Wv, bv);

    dim3 g2(S_LEN / 64, BB * NH);
    attn_kernel<<<g2, 128>>>(mask);

    dim3 g3(DM / 128, (BB * S_LEN) / 128);
    out_proj_kernel<<<g3, 256>>>(Wo, bo, out);
}

// round 6
// speedup vs baseline: 2.1260x; 1.5738x over previous
#include <cuda_runtime.h>
#include <cuda_bf16.h>
#include <cstdint>

#define S_LEN 2048
#define DM    1024
#define NH    16
#define DKH   64
#define BB    2

// scratch: [B,H,S,DK] layouts
__device__ float g_q[BB*NH*S_LEN*DKH];
__device__ float g_k[BB*NH*S_LEN*DKH];
__device__ float g_v[BB*NH*S_LEN*DKH];
__device__ float g_attn[BB*NH*S_LEN*DKH];

// ---------------------------------------------------------------------------
// MMA helpers (warp-level, bf16 in / f32 out)
// ---------------------------------------------------------------------------
__device__ __forceinline__ void ldsm_x4(uint32_t& r0, uint32_t& r1, uint32_t& r2, uint32_t& r3,
                                        uint32_t addr) {
    asm volatile("ldmatrix.sync.aligned.m8n8.x4.shared.b16 {%0,%1,%2,%3}, [%4];"
                 : "=r"(r0), "=r"(r1), "=r"(r2), "=r"(r3) : "r"(addr));
}

__device__ __forceinline__ void ldsm_x4_t(uint32_t& r0, uint32_t& r1, uint32_t& r2, uint32_t& r3,
                                          uint32_t addr) {
    asm volatile("ldmatrix.sync.aligned.m8n8.x4.trans.shared.b16 {%0,%1,%2,%3}, [%4];"
                 : "=r"(r0), "=r"(r1), "=r"(r2), "=r"(r3) : "r"(addr));
}

__device__ __forceinline__ void mma_bf16(float* c, const uint32_t* a, const uint32_t* b) {
    asm volatile(
        "mma.sync.aligned.m16n8k16.row.col.f32.bf16.bf16.f32 "
        "{%0,%1,%2,%3}, {%4,%5,%6,%7}, {%8,%9}, {%0,%1,%2,%3};"
        : "+f"(c[0]), "+f"(c[1]), "+f"(c[2]), "+f"(c[3])
        : "r"(a[0]), "r"(a[1]), "r"(a[2]), "r"(a[3]), "r"(b[0]), "r"(b[1]));
}

// split 8 floats into bf16 hi/lo and store 16B each
__device__ __forceinline__ void split_store(float4 u0, float4 u1,
                                            __nv_bfloat16* dst_hi, __nv_bfloat16* dst_lo) {
    float x[8] = {u0.x, u0.y, u0.z, u0.w, u1.x, u1.y, u1.z, u1.w};
    __nv_bfloat162 h[4], l[4];
    #pragma unroll
    for (int i = 0; i < 4; i++) {
        float a = x[2*i], b = x[2*i+1];
        __nv_bfloat16 ha = __float2bfloat16_rn(a);
        __nv_bfloat16 hb = __float2bfloat16_rn(b);
        __nv_bfloat16 la = __float2bfloat16_rn(a - __bfloat162float(ha));
        __nv_bfloat16 lb = __float2bfloat16_rn(b - __bfloat162float(hb));
        h[i] = __nv_bfloat162(ha, hb);
        l[i] = __nv_bfloat162(la, lb);
    }
    *(uint4*)dst_hi = *(uint4*)h;
    *(uint4*)dst_lo = *(uint4*)l;
}

// pack 2 floats -> bf16x2 hi reg, bf16x2 lo reg
__device__ __forceinline__ uint32_t pack_split(float a, float b, uint32_t& lo) {
    __nv_bfloat16 ha = __float2bfloat16_rn(a);
    __nv_bfloat16 hb = __float2bfloat16_rn(b);
    __nv_bfloat16 la = __float2bfloat16_rn(a - __bfloat162float(ha));
    __nv_bfloat16 lb = __float2bfloat16_rn(b - __bfloat162float(hb));
    __nv_bfloat162 h2(ha, hb), l2(la, lb);
    lo = *(uint32_t*)&l2;
    return *(uint32_t*)&h2;
}

// smem layout constants for the GEMM kernels
#define LDAB 24            // bf16 per row (16 data + 8 pad -> 48B, conflict-free LDSM)
#define T_A_HI 0
#define T_A_LO (128*LDAB)
#define T_B_HI (2*128*LDAB)
#define T_B_LO (3*128*LDAB)

// ---------------------------------------------------------------------------
// QKV projection (unchanged from R5): bf16-split tensor-core GEMM.
// ---------------------------------------------------------------------------
__global__ __launch_bounds__(256) void qkv_proj_kernel(
    const float* __restrict__ xq, const float* __restrict__ xk, const float* __restrict__ xv,
    const float* __restrict__ Wq, const float* __restrict__ bq,
    const float* __restrict__ Wk, const float* __restrict__ bk,
    const float* __restrict__ Wv, const float* __restrict__ bv)
{
    int z = blockIdx.z;
    const float* X    = (z == 0) ? xq : (z == 1) ? xk : xv;
    const float* W    = (z == 0) ? Wq : (z == 1) ? Wk : Wv;
    const float* bias = (z == 0) ? bq : (z == 1) ? bk : bv;
    float* out        = (z == 0) ? g_q : (z == 1) ? g_k : g_v;

    __shared__ __align__(16) __nv_bfloat16 sm[4*128*LDAB];   // 24 KB

    int tid  = threadIdx.x;
    int lane = tid & 31;
    int wid  = tid >> 5;
    int wm   = wid & 1;
    int wn   = wid >> 1;
    int m0 = blockIdx.y * 128;
    int n0 = blockIdx.x * 128;

    int grow = tid >> 1;
    int gk8  = (tid & 1) * 8;
    const float* Abase = X + (size_t)(m0 + grow) * DM + gk8;
    const float* Bbase = W + (size_t)(n0 + grow) * DM + gk8;
    __nv_bfloat16* sa_hi = sm + T_A_HI + grow * LDAB + gk8;
    __nv_bfloat16* sa_lo = sm + T_A_LO + grow * LDAB + gk8;
    __nv_bfloat16* sb_hi = sm + T_B_HI + grow * LDAB + gk8;
    __nv_bfloat16* sb_lo = sm + T_B_LO + grow * LDAB + gk8;

    uint32_t smem_u32 = (uint32_t)__cvta_generic_to_shared(sm);
    int a_row = lane & 15, a_kh = (lane >> 4) * 8;
    uint32_t adA[4], adAlo[4];
    #pragma unroll
    for (int mt = 0; mt < 4; mt++) {
        int r = wm * 64 + mt * 16 + a_row;
        adA[mt]   = smem_u32 + (uint32_t)(T_A_HI + r * LDAB + a_kh) * 2;
        adAlo[mt] = smem_u32 + (uint32_t)(T_A_LO + r * LDAB + a_kh) * 2;
    }
    int b_nrow = ((lane >> 4) & 1) * 8 + (lane & 7);
    int b_k    = ((lane >> 3) & 1) * 8;
    uint32_t adB[2], adBlo[2];
    #pragma unroll
    for (int p = 0; p < 2; p++) {
        int r = wn * 32 + p * 16 + b_nrow;
        adB[p]   = smem_u32 + (uint32_t)(T_B_HI + r * LDAB + b_k) * 2;
        adBlo[p] = smem_u32 + (uint32_t)(T_B_LO + r * LDAB + b_k) * 2;
    }

    float C[4][4][4] = {};

    float4 a0 = *(const float4*)(Abase + 0);
    float4 a1 = *(const float4*)(Abase + 4);
    float4 b0 = *(const float4*)(Bbase + 0);
    float4 b1 = *(const float4*)(Bbase + 4);

    for (int k0 = 0; k0 < DM; k0 += 16) {
        __syncthreads();
        split_store(a0, a1, sa_hi, sa_lo);
        split_store(b0, b1, sb_hi, sb_lo);
        __syncthreads();
        if (k0 + 16 < DM) {
            a0 = *(const float4*)(Abase + k0 + 16);
            a1 = *(const float4*)(Abase + k0 + 20);
            b0 = *(const float4*)(Bbase + k0 + 16);
            b1 = *(const float4*)(Bbase + k0 + 20);
        }

        uint32_t A[4][4], Bh[4][2], Bl[4][2];
        #pragma unroll
        for (int mt = 0; mt < 4; mt++)
            ldsm_x4(A[mt][0], A[mt][1], A[mt][2], A[mt][3], adA[mt]);
        #pragma unroll
        for (int p = 0; p < 2; p++) {
            uint32_t r0, r1, r2, r3;
            ldsm_x4(r0, r1, r2, r3, adB[p]);
            Bh[p*2+0][0] = r0; Bh[p*2+0][1] = r1;
            Bh[p*2+1][0] = r2; Bh[p*2+1][1] = r3;
            ldsm_x4(r0, r1, r2, r3, adBlo[p]);
            Bl[p*2+0][0] = r0; Bl[p*2+0][1] = r1;
            Bl[p*2+1][0] = r2; Bl[p*2+1][1] = r3;
        }
        #pragma unroll
        for (int mt = 0; mt < 4; mt++)
            #pragma unroll
            for (int nt = 0; nt < 4; nt++) {
                mma_bf16(C[mt][nt], A[mt], Bh[nt]);
                mma_bf16(C[mt][nt], A[mt], Bl[nt]);
            }
        #pragma unroll
        for (int mt = 0; mt < 4; mt++)
            ldsm_x4(A[mt][0], A[mt][1], A[mt][2], A[mt][3], adAlo[mt]);
        #pragma unroll
        for (int mt = 0; mt < 4; mt++)
            #pragma unroll
            for (int nt = 0; nt < 4; nt++)
                mma_bf16(C[mt][nt], A[mt], Bh[nt]);
    }

    int crow = lane >> 2;
    int ccol = (lane & 3) * 2;
    #pragma unroll
    for (int nt = 0; nt < 4; nt++) {
        int n = n0 + wn * 32 + nt * 8 + ccol;
        int h = n >> 6, dk = n & 63;
        float bi0 = bias[n], bi1 = bias[n + 1];
        #pragma unroll
        for (int mt = 0; mt < 4; mt++) {
            #pragma unroll
            for (int half = 0; half < 2; half++) {
                int m = m0 + wm * 64 + mt * 16 + crow + half * 8;
                int b_ = m >> 11, s = m & 2047;
                float* op = out + (((size_t)(b_ * NH + h)) * S_LEN + s) * DKH + dk;
                float2 r = make_float2(C[mt][nt][half*2+0] + bi0, C[mt][nt][half*2+1] + bi1);
                *(float2*)op = r;
            }
        }
    }
}

// ---------------------------------------------------------------------------
// Output projection (unchanged from R5).
// ---------------------------------------------------------------------------
__global__ __launch_bounds__(256) void out_proj_kernel(
    const float* __restrict__ Wo, const float* __restrict__ bo, float* __restrict__ out)
{
    __shared__ __align__(16) __nv_bfloat16 sm[4*128*LDAB];

    int tid  = threadIdx.x;
    int lane = tid & 31;
    int wid  = tid >> 5;
    int wm   = wid & 1;
    int wn   = wid >> 1;
    int m0 = blockIdx.y * 128;
    int n0 = blockIdx.x * 128;

    int grow = tid >> 1;
    int gk8  = (tid & 1) * 8;
    int m  = m0 + grow;
    int b_ = m >> 11, ss = m & 2047;
    const float* arow = g_attn + ((size_t)b_ * NH) * S_LEN * DKH + (size_t)ss * DKH;
    const float* Bbase = Wo + (size_t)(n0 + grow) * DM + gk8;
    __nv_bfloat16* sa_hi = sm + T_A_HI + grow * LDAB + gk8;
    __nv_bfloat16* sa_lo = sm + T_A_LO + grow * LDAB + gk8;
    __nv_bfloat16* sb_hi = sm + T_B_HI + grow * LDAB + gk8;
    __nv_bfloat16* sb_lo = sm + T_B_LO + grow * LDAB + gk8;

    auto lda = [&](int k) -> float4 {
        return *(const float4*)(arow + (size_t)(k >> 6) * (S_LEN * DKH) + (k & 63));
    };

    uint32_t smem_u32 = (uint32_t)__cvta_generic_to_shared(sm);
    int a_row = lane & 15, a_kh = (lane >> 4) * 8;
    uint32_t adA[4], adAlo[4];
    #pragma unroll
    for (int mt = 0; mt < 4; mt++) {
        int r = wm * 64 + mt * 16 + a_row;
        adA[mt]   = smem_u32 + (uint32_t)(T_A_HI + r * LDAB + a_kh) * 2;
        adAlo[mt] = smem_u32 + (uint32_t)(T_A_LO + r * LDAB + a_kh) * 2;
    }
    int b_nrow = ((lane >> 4) & 1) * 8 + (lane & 7);
    int b_k    = ((lane >> 3) & 1) * 8;
    uint32_t adB[2], adBlo[2];
    #pragma unroll
    for (int p = 0; p < 2; p++) {
        int r = wn * 32 + p * 16 + b_nrow;
        adB[p]   = smem_u32 + (uint32_t)(T_B_HI + r * LDAB + b_k) * 2;
        adBlo[p] = smem_u32 + (uint32_t)(T_B_LO + r * LDAB + b_k) * 2;
    }

    float C[4][4][4] = {};

    float4 a0 = lda(gk8);
    float4 a1 = lda(gk8 + 4);
    float4 b0 = *(const float4*)(Bbase + 0);
    float4 b1 = *(const float4*)(Bbase + 4);

    for (int k0 = 0; k0 < DM; k0 += 16) {
        __syncthreads();
        split_store(a0, a1, sa_hi, sa_lo);
        split_store(b0, b1, sb_hi, sb_lo);
        __syncthreads();
        if (k0 + 16 < DM) {
            a0 = lda(k0 + 16 + gk8);
            a1 = lda(k0 + 16 + gk8 + 4);
            b0 = *(const float4*)(Bbase + k0 + 16);
            b1 = *(const float4*)(Bbase + k0 + 20);
        }

        uint32_t A[4][4], Bh[4][2], Bl[4][2];
        #pragma unroll
        for (int mt = 0; mt < 4; mt++)
            ldsm_x4(A[mt][0], A[mt][1], A[mt][2], A[mt][3], adA[mt]);
        #pragma unroll
        for (int p = 0; p < 2; p++) {
            uint32_t r0, r1, r2, r3;
            ldsm_x4(r0, r1, r2, r3, adB[p]);
            Bh[p*2+0][0] = r0; Bh[p*2+0][1] = r1;
            Bh[p*2+1][0] = r2; Bh[p*2+1][1] = r3;
            ldsm_x4(r0, r1, r2, r3, adBlo[p]);
            Bl[p*2+0][0] = r0; Bl[p*2+0][1] = r1;
            Bl[p*2+1][0] = r2; Bl[p*2+1][1] = r3;
        }
        #pragma unroll
        for (int mt = 0; mt < 4; mt++)
            #pragma unroll
            for (int nt = 0; nt < 4; nt++) {
                mma_bf16(C[mt][nt], A[mt], Bh[nt]);
                mma_bf16(C[mt][nt], A[mt], Bl[nt]);
            }
        #pragma unroll
        for (int mt = 0; mt < 4; mt++)
            ldsm_x4(A[mt][0], A[mt][1], A[mt][2], A[mt][3], adAlo[mt]);
        #pragma unroll
        for (int mt = 0; mt < 4; mt++)
            #pragma unroll
            for (int nt = 0; nt < 4; nt++)
                mma_bf16(C[mt][nt], A[mt], Bh[nt]);
    }

    int crow = lane >> 2;
    int ccol = (lane & 3) * 2;
    #pragma unroll
    for (int nt = 0; nt < 4; nt++) {
        int n = n0 + wn * 32 + nt * 8 + ccol;
        float bi0 = bo[n], bi1 = bo[n + 1];
        #pragma unroll
        for (int mt = 0; mt < 4; mt++) {
            #pragma unroll
            for (int half = 0; half < 2; half++) {
                int mr = m0 + wm * 64 + mt * 16 + crow + half * 8;
                float2 r = make_float2(C[mt][nt][half*2+0] + bi0, C[mt][nt][half*2+1] + bi1);
                *(float2*)(out + (size_t)mr * DM + n) = r;
            }
        }
    }
}

// ---------------------------------------------------------------------------
// Flash attention, tensor-core version (FA2 register pipeline, bf16-split).
// CTA: 128 q rows x one (b,h); 8 warps x 16 q rows; kv tiles of 64.
// Smem: bufA = Q-hi stage / K hi(rows 0-63)+lo(64-127); bufB = Q-lo / V hi+lo.
// ---------------------------------------------------------------------------
#define LDK 72

__global__ __launch_bounds__(256) void attn_kernel(const int* __restrict__ mask)
{
    __shared__ __align__(16) __nv_bfloat16 bufA[128*LDK];   // 18.4 KB
    __shared__ __align__(16) __nv_bfloat16 bufB[128*LDK];   // 18.4 KB

    int tid  = threadIdx.x;
    int lane = tid & 31;
    int warp = tid >> 5;              // q-row tile = warp*16
    int bh = blockIdx.y;
    int b  = bh >> 4;
    int q0 = blockIdx.x * 128;

    const float* Qg = g_q + (size_t)bh * S_LEN * DKH;
    const float* Kg = g_k + (size_t)bh * S_LEN * DKH;
    const float* Vg = g_v + (size_t)bh * S_LEN * DKH;

    uint32_t baseA = (uint32_t)__cvta_generic_to_shared(bufA);
    uint32_t baseB = (uint32_t)__cvta_generic_to_shared(bufB);

    // ---- stage Q: hi -> bufA, lo -> bufB ----
    {
        int row = tid >> 1;
        int c0 = (tid & 1) * 32;
        const float* src = Qg + (size_t)(q0 + row) * DKH + c0;
        #pragma unroll
        for (int c = 0; c < 32; c += 8) {
            float4 u0 = *(const float4*)(src + c);
            float4 u1 = *(const float4*)(src + c + 4);
            split_store(u0, u1, bufA + row*LDK + c0 + c, bufB + row*LDK + c0 + c);
        }
    }
    __syncthreads();

    // ---- Q A-fragments (resident all kernel): [ktile over d][4 regs] ----
    uint32_t Qh[4][4], Ql[4][4];
    {
        int a_row = lane & 15, a_kh = (lane >> 4) * 8;
        #pragma unroll
        for (int kt = 0; kt < 4; kt++) {
            uint32_t off = (uint32_t)((warp*16 + a_row)*LDK + kt*16 + a_kh) * 2;
            ldsm_x4(Qh[kt][0], Qh[kt][1], Qh[kt][2], Qh[kt][3], baseA + off);
            ldsm_x4(Ql[kt][0], Ql[kt][1], Ql[kt][2], Ql[kt][3], baseB + off);
        }
    }

    float m_i[2] = {-1e30f, -1e30f};
    float l_i[2] = {0.f, 0.f};
    float O[8][4] = {};

    int r0 = lane >> 2;            // row within warp's 16-tile
    int c2 = (lane & 3) * 2;       // col pair within 8-wide n tile
    int b_nrow = ((lane >> 4) & 1) * 8 + (lane & 7);
    int b_k    = ((lane >> 3) & 1) * 8;
    int v_row  = ((lane >> 3) & 1) * 8 + (lane & 7);
    int v_col  = (lane >> 4) * 8;

    for (int k0 = 0; k0 < S_LEN; k0 += 64) {
        __syncthreads();   // prior tile's ldmatrix reads done (and Q frags loaded)
        {
            int row = tid >> 2;
            int c0 = (tid & 3) * 16;
            const float* ks = Kg + (size_t)(k0 + row) * DKH + c0;
            const float* vs = Vg + (size_t)(k0 + row) * DKH + c0;
            #pragma unroll
            for (int c = 0; c < 16; c += 8) {
                float4 u0 = *(const float4*)(ks + c);
                float4 u1 = *(const float4*)(ks + c + 4);
                split_store(u0, u1, bufA + row*LDK + c0 + c, bufA + (64+row)*LDK + c0 + c);
                float4 w0 = *(const float4*)(vs + c);
                float4 w1 = *(const float4*)(vs + c + 4);
                split_store(w0, w1, bufB + row*LDK + c0 + c, bufB + (64+row)*LDK + c0 + c);
            }
        }
        __syncthreads();

        // ---- S = Q K^T : S[nt over kv64][4] ----
        float S[8][4] = {};
        #pragma unroll
        for (int kt = 0; kt < 4; kt++) {
            uint32_t Bh[8][2], Bl[8][2];
            #pragma unroll
            for (int np = 0; np < 4; np++) {
                uint32_t x0, x1, x2, x3;
                uint32_t off = (uint32_t)((np*16 + b_nrow)*LDK + kt*16 + b_k) * 2;
                ldsm_x4(x0, x1, x2, x3, baseA + off);
                Bh[np*2+0][0] = x0; Bh[np*2+0][1] = x1;
                Bh[np*2+1][0] = x2; Bh[np*2+1][1] = x3;
                ldsm_x4(x0, x1, x2, x3, baseA + off + 64*LDK*2);
                Bl[np*2+0][0] = x0; Bl[np*2+0][1] = x1;
                Bl[np*2+1][0] = x2; Bl[np*2+1][1] = x3;
            }
            #pragma unroll
            for (int nt = 0; nt < 8; nt++) {
                mma_bf16(S[nt], Qh[kt], Bh[nt]);
                mma_bf16(S[nt], Qh[kt], Bl[nt]);
                mma_bf16(S[nt], Ql[kt], Bh[nt]);
            }
        }

        // ---- mask + scale ----
        const int* mrow0 = mask + ((size_t)b * S_LEN + q0 + warp*16 + r0) * S_LEN + k0 + c2;
        const int* mrow1 = mrow0 + 8 * S_LEN;
        #pragma unroll
        for (int nt = 0; nt < 8; nt++) {
            int2 mv0 = *(const int2*)(mrow0 + nt*8);
            int2 mv1 = *(const int2*)(mrow1 + nt*8);
            S[nt][0] = mv0.x ? S[nt][0] * 0.125f : -1e9f;
            S[nt][1] = mv0.y ? S[nt][1] * 0.125f : -1e9f;
            S[nt][2] = mv1.x ? S[nt][2] * 0.125f : -1e9f;
            S[nt][3] = mv1.y ? S[nt][3] * 0.125f : -1e9f;
        }

        // ---- online softmax (2 rows per thread, quad shfl reduce) ----
        #pragma unroll
        for (int h = 0; h < 2; h++) {
            float mx = -1e30f;
            #pragma unroll
            for (int nt = 0; nt < 8; nt++)
                mx = fmaxf(mx, fmaxf(S[nt][2*h], S[nt][2*h+1]));
            mx = fmaxf(mx, __shfl_xor_sync(0xffffffffu, mx, 1));
            mx = fmaxf(mx, __shfl_xor_sync(0xffffffffu, mx, 2));
            float mnew  = fmaxf(m_i[h], mx);
            float alpha = __expf(m_i[h] - mnew);
            m_i[h] = mnew;
            float ls = 0.f;
            #pragma unroll
            for (int nt = 0; nt < 8; nt++) {
                S[nt][2*h]   = __expf(S[nt][2*h]   - mnew);
                S[nt][2*h+1] = __expf(S[nt][2*h+1] - mnew);
                ls += S[nt][2*h] + S[nt][2*h+1];
            }
            ls += __shfl_xor_sync(0xffffffffu, ls, 1);
            ls += __shfl_xor_sync(0xffffffffu, ls, 2);
            l_i[h] = l_i[h] * alpha + ls;
            #pragma unroll
            for (int nt = 0; nt < 8; nt++) { O[nt][2*h] *= alpha; O[nt][2*h+1] *= alpha; }
        }

        // ---- O += P V : P from S-fragments (register identity), V via ldsm.trans ----
        #pragma unroll
        for (int kt = 0; kt < 4; kt++) {
            uint32_t Ah[4], Al[4];
            Ah[0] = pack_split(S[2*kt+0][0], S[2*kt+0][1], Al[0]);
            Ah[1] = pack_split(S[2*kt+0][2], S[2*kt+0][3], Al[1]);
            Ah[2] = pack_split(S[2*kt+1][0], S[2*kt+1][1], Al[2]);
            Ah[3] = pack_split(S[2*kt+1][2], S[2*kt+1][3], Al[3]);

            uint32_t Vh[8][2], Vl[8][2];
            #pragma unroll
            for (int np = 0; np < 4; np++) {
                uint32_t x0, x1, x2, x3;
                uint32_t off = (uint32_t)((kt*16 + v_row)*LDK + np*16 + v_col) * 2;
                ldsm_x4_t(x0, x1, x2, x3, baseB + off);
                Vh[np*2+0][0] = x0; Vh[np*2+0][1] = x1;
                Vh[np*2+1][0] = x2; Vh[np*2+1][1] = x3;
                ldsm_x4_t(x0, x1, x2, x3, baseB + off + 64*LDK*2);
                Vl[np*2+0][0] = x0; Vl[np*2+0][1] = x1;
                Vl[np*2+1][0] = x2; Vl[np*2+1][1] = x3;
            }
            #pragma unroll
            for (int nt = 0; nt < 8; nt++) {
                mma_bf16(O[nt], Ah, Vh[nt]);
                mma_bf16(O[nt], Ah, Vl[nt]);
                mma_bf16(O[nt], Al, Vh[nt]);
            }
        }
    }

    // ---- finalize: divide by l, write [B,H,S,DK] ----
    float inv0 = 1.0f / l_i[0];
    float inv1 = 1.0f / l_i[1];
    float* orow0 = g_attn + ((size_t)bh * S_LEN + q0 + warp*16 + r0) * DKH + c2;
    float* orow1 = orow0 + 8 * DKH;
    #pragma unroll
    for (int nt = 0; nt < 8; nt++) {
        *(float2*)(orow0 + nt*8) = make_float2(O[nt][0] * inv0, O[nt][1] * inv0);
        *(float2*)(orow1 + nt*8) = make_float2(O[nt][2] * inv1, O[nt][3] * inv1);
    }
}

extern "C" void kernel_launch(void* const* d_in, const int* in_sizes, int n_in,
                              void* d_out, int out_size)
{
    const float* query = (const float*)d_in[0];
    const float* key_  = (const float*)d_in[1];
    const float* value = (const float*)d_in[2];
    const int*   mask  = (const int*)d_in[3];
    const float* Wq = (const float*)d_in[4];
    const float* bq = (const float*)d_in[5];
    const float* Wk = (const float*)d_in[6];
    const float* bk = (const float*)d_in[7];
    const float* Wv = (const float*)d_in[8];
    const float* bv = (const float*)d_in[9];
    const float* Wo = (const float*)d_in[10];
    const float* bo = (const float*)d_in[11];
    float* out = (float*)d_out;

    dim3 g1(DM / 128, (BB * S_LEN) / 128, 3);
    qkv_proj_kernel<<<g1, 256>>>(query, key_, value, Wq, bq, Wk, bk, Wv, bv);

    dim3 g2(S_LEN / 128, BB * NH);
    attn_kernel<<<g2, 256>>>(mask);

    dim3 g3(DM / 128, (BB * S_LEN) / 128);
    out_proj_kernel<<<g3, 256>>>(Wo, bo, out);
}

// round 7
// speedup vs baseline: 2.3316x; 1.0967x over previous
#include <cuda_runtime.h>
#include <cuda_bf16.h>
#include <cstdint>

#define S_LEN 2048
#define DM    1024
#define NH    16
#define DKH   64
#define BB    2

// scratch: [B,H,S,DK] layouts
__device__ float g_q[BB*NH*S_LEN*DKH];
__device__ float g_k[BB*NH*S_LEN*DKH];
__device__ float g_v[BB*NH*S_LEN*DKH];
__device__ float g_attn[BB*NH*S_LEN*DKH];

// ---------------------------------------------------------------------------
// MMA helpers (warp-level, bf16 in / f32 out)
// ---------------------------------------------------------------------------
__device__ __forceinline__ void ldsm_x4(uint32_t& r0, uint32_t& r1, uint32_t& r2, uint32_t& r3,
                                        uint32_t addr) {
    asm volatile("ldmatrix.sync.aligned.m8n8.x4.shared.b16 {%0,%1,%2,%3}, [%4];"
                 : "=r"(r0), "=r"(r1), "=r"(r2), "=r"(r3) : "r"(addr));
}

__device__ __forceinline__ void ldsm_x4_t(uint32_t& r0, uint32_t& r1, uint32_t& r2, uint32_t& r3,
                                          uint32_t addr) {
    asm volatile("ldmatrix.sync.aligned.m8n8.x4.trans.shared.b16 {%0,%1,%2,%3}, [%4];"
                 : "=r"(r0), "=r"(r1), "=r"(r2), "=r"(r3) : "r"(addr));
}

__device__ __forceinline__ void mma_bf16(float* c, const uint32_t* a, const uint32_t* b) {
    asm volatile(
        "mma.sync.aligned.m16n8k16.row.col.f32.bf16.bf16.f32 "
        "{%0,%1,%2,%3}, {%4,%5,%6,%7}, {%8,%9}, {%0,%1,%2,%3};"
        : "+f"(c[0]), "+f"(c[1]), "+f"(c[2]), "+f"(c[3])
        : "r"(a[0]), "r"(a[1]), "r"(a[2]), "r"(a[3]), "r"(b[0]), "r"(b[1]));
}

// split 8 floats into bf16 hi/lo and store 16B each
__device__ __forceinline__ void split_store(float4 u0, float4 u1,
                                            __nv_bfloat16* dst_hi, __nv_bfloat16* dst_lo) {
    float x[8] = {u0.x, u0.y, u0.z, u0.w, u1.x, u1.y, u1.z, u1.w};
    __nv_bfloat162 h[4], l[4];
    #pragma unroll
    for (int i = 0; i < 4; i++) {
        float a = x[2*i], b = x[2*i+1];
        __nv_bfloat16 ha = __float2bfloat16_rn(a);
        __nv_bfloat16 hb = __float2bfloat16_rn(b);
        __nv_bfloat16 la = __float2bfloat16_rn(a - __bfloat162float(ha));
        __nv_bfloat16 lb = __float2bfloat16_rn(b - __bfloat162float(hb));
        h[i] = __nv_bfloat162(ha, hb);
        l[i] = __nv_bfloat162(la, lb);
    }
    *(uint4*)dst_hi = *(uint4*)h;
    *(uint4*)dst_lo = *(uint4*)l;
}

// pack 2 floats -> bf16x2 hi reg, bf16x2 lo reg
__device__ __forceinline__ uint32_t pack_split(float a, float b, uint32_t& lo) {
    __nv_bfloat16 ha = __float2bfloat16_rn(a);
    __nv_bfloat16 hb = __float2bfloat16_rn(b);
    __nv_bfloat16 la = __float2bfloat16_rn(a - __bfloat162float(ha));
    __nv_bfloat16 lb = __float2bfloat16_rn(b - __bfloat162float(hb));
    __nv_bfloat162 h2(ha, hb), l2(la, lb);
    lo = *(uint32_t*)&l2;
    return *(uint32_t*)&h2;
}

// smem layout constants for the GEMM kernels
#define LDAB 24                 // bf16 per row (16 data + 8 pad)
#define T_A_HI 0
#define T_A_LO (128*LDAB)
#define T_B_HI (2*128*LDAB)
#define T_B_LO (3*128*LDAB)
#define G_STAGE_EL (4*128*LDAB)     // elements per stage = 12288
#define G_STAGE_B  (G_STAGE_EL*2)   // bytes per stage = 24576

// ---------------------------------------------------------------------------
// QKV projection: double-buffered bf16-split tensor-core GEMM, 1 barrier/step.
// ---------------------------------------------------------------------------
__global__ __launch_bounds__(256) void qkv_proj_kernel(
    const float* __restrict__ xq, const float* __restrict__ xk, const float* __restrict__ xv,
    const float* __restrict__ Wq, const float* __restrict__ bq,
    const float* __restrict__ Wk, const float* __restrict__ bk,
    const float* __restrict__ Wv, const float* __restrict__ bv)
{
    int z = blockIdx.z;
    const float* X    = (z == 0) ? xq : (z == 1) ? xk : xv;
    const float* W    = (z == 0) ? Wq : (z == 1) ? Wk : Wv;
    const float* bias = (z == 0) ? bq : (z == 1) ? bk : bv;
    float* out        = (z == 0) ? g_q : (z == 1) ? g_k : g_v;

    __shared__ __align__(16) __nv_bfloat16 sm[2*G_STAGE_EL];   // 48 KB exactly

    int tid  = threadIdx.x;
    int lane = tid & 31;
    int wid  = tid >> 5;
    int wm   = wid & 1;
    int wn   = wid >> 1;
    int m0 = blockIdx.y * 128;
    int n0 = blockIdx.x * 128;

    int grow = tid >> 1;
    int gk8  = (tid & 1) * 8;
    const float* Abase = X + (size_t)(m0 + grow) * DM + gk8;
    const float* Bbase = W + (size_t)(n0 + grow) * DM + gk8;
    __nv_bfloat16* sa_hi = sm + T_A_HI + grow * LDAB + gk8;
    __nv_bfloat16* sa_lo = sm + T_A_LO + grow * LDAB + gk8;
    __nv_bfloat16* sb_hi = sm + T_B_HI + grow * LDAB + gk8;
    __nv_bfloat16* sb_lo = sm + T_B_LO + grow * LDAB + gk8;

    uint32_t smem_u32 = (uint32_t)__cvta_generic_to_shared(sm);
    int a_row = lane & 15, a_kh = (lane >> 4) * 8;
    uint32_t adA[4], adAlo[4];
    #pragma unroll
    for (int mt = 0; mt < 4; mt++) {
        int r = wm * 64 + mt * 16 + a_row;
        adA[mt]   = smem_u32 + (uint32_t)(T_A_HI + r * LDAB + a_kh) * 2;
        adAlo[mt] = smem_u32 + (uint32_t)(T_A_LO + r * LDAB + a_kh) * 2;
    }
    int b_nrow = ((lane >> 4) & 1) * 8 + (lane & 7);
    int b_k    = ((lane >> 3) & 1) * 8;
    uint32_t adB[2], adBlo[2];
    #pragma unroll
    for (int p = 0; p < 2; p++) {
        int r = wn * 32 + p * 16 + b_nrow;
        adB[p]   = smem_u32 + (uint32_t)(T_B_HI + r * LDAB + b_k) * 2;
        adBlo[p] = smem_u32 + (uint32_t)(T_B_LO + r * LDAB + b_k) * 2;
    }

    float C[4][4][4] = {};

    float4 a0 = *(const float4*)(Abase + 0);
    float4 a1 = *(const float4*)(Abase + 4);
    float4 b0 = *(const float4*)(Bbase + 0);
    float4 b1 = *(const float4*)(Bbase + 4);

    // prologue: fill stage 0
    split_store(a0, a1, sa_hi, sa_lo);
    split_store(b0, b1, sb_hi, sb_lo);
    __syncthreads();

    uint32_t curB = 0;       // byte offset of stage being computed
    int      curE = 0;       // element offset

    for (int k0 = 0; k0 < DM; k0 += 16) {
        bool more = (k0 + 16) < DM;
        if (more) {
            a0 = *(const float4*)(Abase + k0 + 16);
            a1 = *(const float4*)(Abase + k0 + 20);
            b0 = *(const float4*)(Bbase + k0 + 16);
            b1 = *(const float4*)(Bbase + k0 + 20);
        }

        uint32_t A[4][4], Bh[4][2], Bl[4][2];
        #pragma unroll
        for (int mt = 0; mt < 4; mt++)
            ldsm_x4(A[mt][0], A[mt][1], A[mt][2], A[mt][3], adA[mt] + curB);
        #pragma unroll
        for (int p = 0; p < 2; p++) {
            uint32_t r0, r1, r2, r3;
            ldsm_x4(r0, r1, r2, r3, adB[p] + curB);
            Bh[p*2+0][0] = r0; Bh[p*2+0][1] = r1;
            Bh[p*2+1][0] = r2; Bh[p*2+1][1] = r3;
            ldsm_x4(r0, r1, r2, r3, adBlo[p] + curB);
            Bl[p*2+0][0] = r0; Bl[p*2+0][1] = r1;
            Bl[p*2+1][0] = r2; Bl[p*2+1][1] = r3;
        }
        #pragma unroll
        for (int mt = 0; mt < 4; mt++)
            #pragma unroll
            for (int nt = 0; nt < 4; nt++) {
                mma_bf16(C[mt][nt], A[mt], Bh[nt]);
                mma_bf16(C[mt][nt], A[mt], Bl[nt]);
            }
        #pragma unroll
        for (int mt = 0; mt < 4; mt++)
            ldsm_x4(A[mt][0], A[mt][1], A[mt][2], A[mt][3], adAlo[mt] + curB);
        #pragma unroll
        for (int mt = 0; mt < 4; mt++)
            #pragma unroll
            for (int nt = 0; nt < 4; nt++)
                mma_bf16(C[mt][nt], A[mt], Bh[nt]);

        if (more) {
            int nx = curE ^ G_STAGE_EL;
            split_store(a0, a1, sa_hi + nx, sa_lo + nx);
            split_store(b0, b1, sb_hi + nx, sb_lo + nx);
        }
        __syncthreads();
        curB ^= G_STAGE_B;
        curE ^= G_STAGE_EL;
    }

    int crow = lane >> 2;
    int ccol = (lane & 3) * 2;
    #pragma unroll
    for (int nt = 0; nt < 4; nt++) {
        int n = n0 + wn * 32 + nt * 8 + ccol;
        int h = n >> 6, dk = n & 63;
        float bi0 = bias[n], bi1 = bias[n + 1];
        #pragma unroll
        for (int mt = 0; mt < 4; mt++) {
            #pragma unroll
            for (int half = 0; half < 2; half++) {
                int m = m0 + wm * 64 + mt * 16 + crow + half * 8;
                int b_ = m >> 11, s = m & 2047;
                float* op = out + (((size_t)(b_ * NH + h)) * S_LEN + s) * DKH + dk;
                float2 r = make_float2(C[mt][nt][half*2+0] + bi0, C[mt][nt][half*2+1] + bi1);
                *(float2*)op = r;
            }
        }
    }
}

// ---------------------------------------------------------------------------
// Output projection: same double-buffered structure, head-gathered A.
// ---------------------------------------------------------------------------
__global__ __launch_bounds__(256) void out_proj_kernel(
    const float* __restrict__ Wo, const float* __restrict__ bo, float* __restrict__ out)
{
    __shared__ __align__(16) __nv_bfloat16 sm[2*G_STAGE_EL];

    int tid  = threadIdx.x;
    int lane = tid & 31;
    int wid  = tid >> 5;
    int wm   = wid & 1;
    int wn   = wid >> 1;
    int m0 = blockIdx.y * 128;
    int n0 = blockIdx.x * 128;

    int grow = tid >> 1;
    int gk8  = (tid & 1) * 8;
    int m  = m0 + grow;
    int b_ = m >> 11, ss = m & 2047;
    const float* arow = g_attn + ((size_t)b_ * NH) * S_LEN * DKH + (size_t)ss * DKH;
    const float* Bbase = Wo + (size_t)(n0 + grow) * DM + gk8;
    __nv_bfloat16* sa_hi = sm + T_A_HI + grow * LDAB + gk8;
    __nv_bfloat16* sa_lo = sm + T_A_LO + grow * LDAB + gk8;
    __nv_bfloat16* sb_hi = sm + T_B_HI + grow * LDAB + gk8;
    __nv_bfloat16* sb_lo = sm + T_B_LO + grow * LDAB + gk8;

    auto lda = [&](int k) -> float4 {
        return *(const float4*)(arow + (size_t)(k >> 6) * (S_LEN * DKH) + (k & 63));
    };

    uint32_t smem_u32 = (uint32_t)__cvta_generic_to_shared(sm);
    int a_row = lane & 15, a_kh = (lane >> 4) * 8;
    uint32_t adA[4], adAlo[4];
    #pragma unroll
    for (int mt = 0; mt < 4; mt++) {
        int r = wm * 64 + mt * 16 + a_row;
        adA[mt]   = smem_u32 + (uint32_t)(T_A_HI + r * LDAB + a_kh) * 2;
        adAlo[mt] = smem_u32 + (uint32_t)(T_A_LO + r * LDAB + a_kh) * 2;
    }
    int b_nrow = ((lane >> 4) & 1) * 8 + (lane & 7);
    int b_k    = ((lane >> 3) & 1) * 8;
    uint32_t adB[2], adBlo[2];
    #pragma unroll
    for (int p = 0; p < 2; p++) {
        int r = wn * 32 + p * 16 + b_nrow;
        adB[p]   = smem_u32 + (uint32_t)(T_B_HI + r * LDAB + b_k) * 2;
        adBlo[p] = smem_u32 + (uint32_t)(T_B_LO + r * LDAB + b_k) * 2;
    }

    float C[4][4][4] = {};

    float4 a0 = lda(gk8);
    float4 a1 = lda(gk8 + 4);
    float4 b0 = *(const float4*)(Bbase + 0);
    float4 b1 = *(const float4*)(Bbase + 4);

    split_store(a0, a1, sa_hi, sa_lo);
    split_store(b0, b1, sb_hi, sb_lo);
    __syncthreads();

    uint32_t curB = 0;
    int      curE = 0;

    for (int k0 = 0; k0 < DM; k0 += 16) {
        bool more = (k0 + 16) < DM;
        if (more) {
            a0 = lda(k0 + 16 + gk8);
            a1 = lda(k0 + 16 + gk8 + 4);
            b0 = *(const float4*)(Bbase + k0 + 16);
            b1 = *(const float4*)(Bbase + k0 + 20);
        }

        uint32_t A[4][4], Bh[4][2], Bl[4][2];
        #pragma unroll
        for (int mt = 0; mt < 4; mt++)
            ldsm_x4(A[mt][0], A[mt][1], A[mt][2], A[mt][3], adA[mt] + curB);
        #pragma unroll
        for (int p = 0; p < 2; p++) {
            uint32_t r0, r1, r2, r3;
            ldsm_x4(r0, r1, r2, r3, adB[p] + curB);
            Bh[p*2+0][0] = r0; Bh[p*2+0][1] = r1;
            Bh[p*2+1][0] = r2; Bh[p*2+1][1] = r3;
            ldsm_x4(r0, r1, r2, r3, adBlo[p] + curB);
            Bl[p*2+0][0] = r0; Bl[p*2+0][1] = r1;
            Bl[p*2+1][0] = r2; Bl[p*2+1][1] = r3;
        }
        #pragma unroll
        for (int mt = 0; mt < 4; mt++)
            #pragma unroll
            for (int nt = 0; nt < 4; nt++) {
                mma_bf16(C[mt][nt], A[mt], Bh[nt]);
                mma_bf16(C[mt][nt], A[mt], Bl[nt]);
            }
        #pragma unroll
        for (int mt = 0; mt < 4; mt++)
            ldsm_x4(A[mt][0], A[mt][1], A[mt][2], A[mt][3], adAlo[mt] + curB);
        #pragma unroll
        for (int mt = 0; mt < 4; mt++)
            #pragma unroll
            for (int nt = 0; nt < 4; nt++)
                mma_bf16(C[mt][nt], A[mt], Bh[nt]);

        if (more) {
            int nx = curE ^ G_STAGE_EL;
            split_store(a0, a1, sa_hi + nx, sa_lo + nx);
            split_store(b0, b1, sb_hi + nx, sb_lo + nx);
        }
        __syncthreads();
        curB ^= G_STAGE_B;
        curE ^= G_STAGE_EL;
    }

    int crow = lane >> 2;
    int ccol = (lane & 3) * 2;
    #pragma unroll
    for (int nt = 0; nt < 4; nt++) {
        int n = n0 + wn * 32 + nt * 8 + ccol;
        float bi0 = bo[n], bi1 = bo[n + 1];
        #pragma unroll
        for (int mt = 0; mt < 4; mt++) {
            #pragma unroll
            for (int half = 0; half < 2; half++) {
                int mr = m0 + wm * 64 + mt * 16 + crow + half * 8;
                float2 r = make_float2(C[mt][nt][half*2+0] + bi0, C[mt][nt][half*2+1] + bi1);
                *(float2*)(out + (size_t)mr * DM + n) = r;
            }
        }
    }
}

// ---------------------------------------------------------------------------
// Flash attention, double-buffered K/V pipeline + log2-domain softmax.
// CTA: 128 q rows x one (b,h); 8 warps x 16 q rows; kv tiles of 64.
// Dynamic smem: 2 stages x (K hi/lo + V hi/lo) = 2*256*LDK bf16 = 73728 B.
// ---------------------------------------------------------------------------
#define LDK 72
#define A_STAGE_EL (256*LDK)        // elements per stage
#define A_STAGE_B  (A_STAGE_EL*2)   // 36864 bytes

extern __shared__ __nv_bfloat16 dsm[];

__global__ __launch_bounds__(256) void attn_kernel(const int* __restrict__ mask)
{
    const float MSCALE = 0.125f * 1.44269504f;   // (1/8) * log2(e)
    const float MNEG   = -1.442695e9f;           // -1e9 * log2(e)

    int tid  = threadIdx.x;
    int lane = tid & 31;
    int warp = tid >> 5;
    int bh = blockIdx.y;
    int b  = bh >> 4;
    int q0 = blockIdx.x * 128;

    const float* Qg = g_q + (size_t)bh * S_LEN * DKH;
    const float* Kg = g_k + (size_t)bh * S_LEN * DKH;
    const float* Vg = g_v + (size_t)bh * S_LEN * DKH;

    uint32_t base = (uint32_t)__cvta_generic_to_shared(dsm);

    // ---- stage Q into stage0: hi rows 0-127, lo rows 128-255 ----
    {
        int row = tid >> 1;
        int c0 = (tid & 1) * 32;
        const float* src = Qg + (size_t)(q0 + row) * DKH + c0;
        #pragma unroll
        for (int c = 0; c < 32; c += 8) {
            float4 u0 = *(const float4*)(src + c);
            float4 u1 = *(const float4*)(src + c + 4);
            split_store(u0, u1, dsm + row*LDK + c0 + c, dsm + (128+row)*LDK + c0 + c);
        }
    }
    __syncthreads();

    // ---- Q A-fragments (resident all kernel) ----
    uint32_t Qh[4][4], Ql[4][4];
    {
        int a_row = lane & 15, a_kh = (lane >> 4) * 8;
        #pragma unroll
        for (int kt = 0; kt < 4; kt++) {
            uint32_t off = (uint32_t)((warp*16 + a_row)*LDK + kt*16 + a_kh) * 2;
            ldsm_x4(Qh[kt][0], Qh[kt][1], Qh[kt][2], Qh[kt][3], base + off);
            ldsm_x4(Ql[kt][0], Ql[kt][1], Ql[kt][2], Ql[kt][3], base + 128*LDK*2 + off);
        }
    }
    __syncthreads();   // done reading Q staging before overwriting stage0

    // ---- stage kv tile 0 into stage0 ----
    int row4 = tid >> 2;           // 0..63
    int c04  = (tid & 3) * 16;     // 0,16,32,48
    {
        const float* ks = Kg + (size_t)row4 * DKH + c04;
        const float* vs = Vg + (size_t)row4 * DKH + c04;
        #pragma unroll
        for (int c = 0; c < 16; c += 8) {
            float4 u0 = *(const float4*)(ks + c);
            float4 u1 = *(const float4*)(ks + c + 4);
            split_store(u0, u1, dsm + row4*LDK + c04 + c, dsm + (64+row4)*LDK + c04 + c);
            float4 w0 = *(const float4*)(vs + c);
            float4 w1 = *(const float4*)(vs + c + 4);
            split_store(w0, w1, dsm + (128+row4)*LDK + c04 + c, dsm + (192+row4)*LDK + c04 + c);
        }
    }
    __syncthreads();

    float m_i[2] = {-1e30f, -1e30f};
    float l_i[2] = {0.f, 0.f};
    float O[8][4] = {};

    int r0 = lane >> 2;
    int c2 = (lane & 3) * 2;
    int b_nrow = ((lane >> 4) & 1) * 8 + (lane & 7);
    int b_k    = ((lane >> 3) & 1) * 8;
    int v_row  = ((lane >> 3) & 1) * 8 + (lane & 7);
    int v_col  = (lane >> 4) * 8;

    const float* ksp = Kg + (size_t)row4 * DKH + c04;
    const float* vsp = Vg + (size_t)row4 * DKH + c04;

    for (int it = 0; it < S_LEN/64; it++) {
        int cur = it & 1;
        uint32_t sb = base + (uint32_t)cur * A_STAGE_B;
        bool more = it + 1 < S_LEN/64;

        // ---- prefetch next kv tile into registers (hidden behind compute) ----
        float4 pk0, pk1, pk2, pk3, pv0, pv1, pv2, pv3;
        if (more) {
            const float* ks = ksp + (size_t)(it+1) * 64 * DKH;
            const float* vs = vsp + (size_t)(it+1) * 64 * DKH;
            pk0 = *(const float4*)(ks + 0);  pk1 = *(const float4*)(ks + 4);
            pk2 = *(const float4*)(ks + 8);  pk3 = *(const float4*)(ks + 12);
            pv0 = *(const float4*)(vs + 0);  pv1 = *(const float4*)(vs + 4);
            pv2 = *(const float4*)(vs + 8);  pv3 = *(const float4*)(vs + 12);
        }

        // ---- S = Q K^T ----
        float S[8][4] = {};
        #pragma unroll
        for (int kt = 0; kt < 4; kt++) {
            uint32_t Bh[8][2], Bl[8][2];
            #pragma unroll
            for (int np = 0; np < 4; np++) {
                uint32_t x0, x1, x2, x3;
                uint32_t off = sb + (uint32_t)((np*16 + b_nrow)*LDK + kt*16 + b_k) * 2;
                ldsm_x4(x0, x1, x2, x3, off);
                Bh[np*2+0][0] = x0; Bh[np*2+0][1] = x1;
                Bh[np*2+1][0] = x2; Bh[np*2+1][1] = x3;
                ldsm_x4(x0, x1, x2, x3, off + 64*LDK*2);
                Bl[np*2+0][0] = x0; Bl[np*2+0][1] = x1;
                Bl[np*2+1][0] = x2; Bl[np*2+1][1] = x3;
            }
            #pragma unroll
            for (int nt = 0; nt < 8; nt++) {
                mma_bf16(S[nt], Qh[kt], Bh[nt]);
                mma_bf16(S[nt], Qh[kt], Bl[nt]);
                mma_bf16(S[nt], Ql[kt], Bh[nt]);
            }
        }

        // ---- mask + scale (log2 domain) ----
        int k0 = it * 64;
        const int* mrow0 = mask + ((size_t)b * S_LEN + q0 + warp*16 + r0) * S_LEN + k0 + c2;
        const int* mrow1 = mrow0 + 8 * S_LEN;
        #pragma unroll
        for (int nt = 0; nt < 8; nt++) {
            int2 mv0 = *(const int2*)(mrow0 + nt*8);
            int2 mv1 = *(const int2*)(mrow1 + nt*8);
            S[nt][0] = mv0.x ? S[nt][0] * MSCALE : MNEG;
            S[nt][1] = mv0.y ? S[nt][1] * MSCALE : MNEG;
            S[nt][2] = mv1.x ? S[nt][2] * MSCALE : MNEG;
            S[nt][3] = mv1.y ? S[nt][3] * MSCALE : MNEG;
        }

        // ---- online softmax (base-2) ----
        #pragma unroll
        for (int h = 0; h < 2; h++) {
            float mx = -1e30f;
            #pragma unroll
            for (int nt = 0; nt < 8; nt++)
                mx = fmaxf(mx, fmaxf(S[nt][2*h], S[nt][2*h+1]));
            mx = fmaxf(mx, __shfl_xor_sync(0xffffffffu, mx, 1));
            mx = fmaxf(mx, __shfl_xor_sync(0xffffffffu, mx, 2));
            float mnew  = fmaxf(m_i[h], mx);
            float alpha = exp2f(m_i[h] - mnew);
            m_i[h] = mnew;
            float ls = 0.f;
            #pragma unroll
            for (int nt = 0; nt < 8; nt++) {
                S[nt][2*h]   = exp2f(S[nt][2*h]   - mnew);
                S[nt][2*h+1] = exp2f(S[nt][2*h+1] - mnew);
                ls += S[nt][2*h] + S[nt][2*h+1];
            }
            ls += __shfl_xor_sync(0xffffffffu, ls, 1);
            ls += __shfl_xor_sync(0xffffffffu, ls, 2);
            l_i[h] = l_i[h] * alpha + ls;
            #pragma unroll
            for (int nt = 0; nt < 8; nt++) { O[nt][2*h] *= alpha; O[nt][2*h+1] *= alpha; }
        }

        // ---- O += P V ----
        #pragma unroll
        for (int kt = 0; kt < 4; kt++) {
            uint32_t Ah[4], Al[4];
            Ah[0] = pack_split(S[2*kt+0][0], S[2*kt+0][1], Al[0]);
            Ah[1] = pack_split(S[2*kt+0][2], S[2*kt+0][3], Al[1]);
            Ah[2] = pack_split(S[2*kt+1][0], S[2*kt+1][1], Al[2]);
            Ah[3] = pack_split(S[2*kt+1][2], S[2*kt+1][3], Al[3]);

            uint32_t Vh[8][2], Vl[8][2];
            #pragma unroll
            for (int np = 0; np < 4; np++) {
                uint32_t x0, x1, x2, x3;
                uint32_t off = sb + 128*LDK*2 + (uint32_t)((kt*16 + v_row)*LDK + np*16 + v_col) * 2;
                ldsm_x4_t(x0, x1, x2, x3, off);
                Vh[np*2+0][0] = x0; Vh[np*2+0][1] = x1;
                Vh[np*2+1][0] = x2; Vh[np*2+1][1] = x3;
                ldsm_x4_t(x0, x1, x2, x3, off + 64*LDK*2);
                Vl[np*2+0][0] = x0; Vl[np*2+0][1] = x1;
                Vl[np*2+1][0] = x2; Vl[np*2+1][1] = x3;
            }
            #pragma unroll
            for (int nt = 0; nt < 8; nt++) {
                mma_bf16(O[nt], Ah, Vh[nt]);
                mma_bf16(O[nt], Ah, Vl[nt]);
                mma_bf16(O[nt], Al, Vh[nt]);
            }
        }

        // ---- store prefetched tile into the other stage ----
        if (more) {
            __nv_bfloat16* nx = dsm + (cur ^ 1) * A_STAGE_EL;
            split_store(pk0, pk1, nx + row4*LDK + c04,     nx + (64+row4)*LDK + c04);
            split_store(pk2, pk3, nx + row4*LDK + c04 + 8, nx + (64+row4)*LDK + c04 + 8);
            split_store(pv0, pv1, nx + (128+row4)*LDK + c04,     nx + (192+row4)*LDK + c04);
            split_store(pv2, pv3, nx + (128+row4)*LDK + c04 + 8, nx + (192+row4)*LDK + c04 + 8);
        }
        __syncthreads();
    }

    // ---- finalize ----
    float inv0 = 1.0f / l_i[0];
    float inv1 = 1.0f / l_i[1];
    float* orow0 = g_attn + ((size_t)bh * S_LEN + q0 + warp*16 + r0) * DKH + c2;
    float* orow1 = orow0 + 8 * DKH;
    #pragma unroll
    for (int nt = 0; nt < 8; nt++) {
        *(float2*)(orow0 + nt*8) = make_float2(O[nt][0] * inv0, O[nt][1] * inv0);
        *(float2*)(orow1 + nt*8) = make_float2(O[nt][2] * inv1, O[nt][3] * inv1);
    }
}

extern "C" void kernel_launch(void* const* d_in, const int* in_sizes, int n_in,
                              void* d_out, int out_size)
{
    const float* query = (const float*)d_in[0];
    const float* key_  = (const float*)d_in[1];
    const float* value = (const float*)d_in[2];
    const int*   mask  = (const int*)d_in[3];
    const float* Wq = (const float*)d_in[4];
    const float* bq = (const float*)d_in[5];
    const float* Wk = (const float*)d_in[6];
    const float* bk = (const float*)d_in[7];
    const float* Wv = (const float*)d_in[8];
    const float* bv = (const float*)d_in[9];
    const float* Wo = (const float*)d_in[10];
    const float* bo = (const float*)d_in[11];
    float* out = (float*)d_out;

    cudaFuncSetAttribute(attn_kernel, cudaFuncAttributeMaxDynamicSharedMemorySize,
                         2 * A_STAGE_B);

    dim3 g1(DM / 128, (BB * S_LEN) / 128, 3);
    qkv_proj_kernel<<<g1, 256>>>(query, key_, value, Wq, bq, Wk, bk, Wv, bv);

    dim3 g2(S_LEN / 128, BB * NH);
    attn_kernel<<<g2, 256, 2 * A_STAGE_B>>>(mask);

    dim3 g3(DM / 128, (BB * S_LEN) / 128);
    out_proj_kernel<<<g3, 256>>>(Wo, bo, out);
}

// round 8
// speedup vs baseline: 2.5116x; 1.0772x over previous
#include <cuda_runtime.h>
#include <cuda_fp16.h>
#include <cstdint>

#define S_LEN 2048
#define DM    1024
#define NH    16
#define DKH   64
#define BB    2

// scratch: [B,H,S,DK] layouts
__device__ float g_q[BB*NH*S_LEN*DKH];
__device__ float g_k[BB*NH*S_LEN*DKH];
__device__ float g_v[BB*NH*S_LEN*DKH];
__device__ float g_attn[BB*NH*S_LEN*DKH];

// ---------------------------------------------------------------------------
// MMA helpers (warp-level, fp16 in / f32 out)
// ---------------------------------------------------------------------------
__device__ __forceinline__ void ldsm_x4(uint32_t& r0, uint32_t& r1, uint32_t& r2, uint32_t& r3,
                                        uint32_t addr) {
    asm volatile("ldmatrix.sync.aligned.m8n8.x4.shared.b16 {%0,%1,%2,%3}, [%4];"
                 : "=r"(r0), "=r"(r1), "=r"(r2), "=r"(r3) : "r"(addr));
}

__device__ __forceinline__ void ldsm_x4_t(uint32_t& r0, uint32_t& r1, uint32_t& r2, uint32_t& r3,
                                          uint32_t addr) {
    asm volatile("ldmatrix.sync.aligned.m8n8.x4.trans.shared.b16 {%0,%1,%2,%3}, [%4];"
                 : "=r"(r0), "=r"(r1), "=r"(r2), "=r"(r3) : "r"(addr));
}

__device__ __forceinline__ void mma_f16(float* c, const uint32_t* a, const uint32_t* b) {
    asm volatile(
        "mma.sync.aligned.m16n8k16.row.col.f32.f16.f16.f32 "
        "{%0,%1,%2,%3}, {%4,%5,%6,%7}, {%8,%9}, {%0,%1,%2,%3};"
        : "+f"(c[0]), "+f"(c[1]), "+f"(c[2]), "+f"(c[3])
        : "r"(a[0]), "r"(a[1]), "r"(a[2]), "r"(a[3]), "r"(b[0]), "r"(b[1]));
}

// split 8 floats into fp16 hi/lo and store 16B each
__device__ __forceinline__ void split_store_h(float4 u0, float4 u1,
                                              __half* dst_hi, __half* dst_lo) {
    float x[8] = {u0.x, u0.y, u0.z, u0.w, u1.x, u1.y, u1.z, u1.w};
    __half2 h[4], l[4];
    #pragma unroll
    for (int i = 0; i < 4; i++) {
        float a = x[2*i], b = x[2*i+1];
        __half ha = __float2half_rn(a);
        __half hb = __float2half_rn(b);
        __half la = __float2half_rn(a - __half2float(ha));
        __half lb = __float2half_rn(b - __half2float(hb));
        h[i] = __halves2half2(ha, hb);
        l[i] = __halves2half2(la, lb);
    }
    *(uint4*)dst_hi = *(uint4*)h;
    *(uint4*)dst_lo = *(uint4*)l;
}

// convert 8 floats to single fp16, store 16B
__device__ __forceinline__ void cvt_store_h(float4 u0, float4 u1, __half* dst) {
    __half2 h[4];
    h[0] = __floats2half2_rn(u0.x, u0.y);
    h[1] = __floats2half2_rn(u0.z, u0.w);
    h[2] = __floats2half2_rn(u1.x, u1.y);
    h[3] = __floats2half2_rn(u1.z, u1.w);
    *(uint4*)dst = *(uint4*)h;
}

__device__ __forceinline__ uint32_t pack_h(float a, float b) {
    __half2 t = __floats2half2_rn(a, b);
    return *(uint32_t*)&t;
}

// smem layout constants for the GEMM kernels
#define LDAB 24                 // fp16 per row (16 data + 8 pad)
#define T_A_HI 0
#define T_A_LO (128*LDAB)
#define T_B_HI (2*128*LDAB)
#define T_B_LO (3*128*LDAB)
#define G_STAGE_EL (4*128*LDAB)     // elements per stage = 12288
#define G_STAGE_B  (G_STAGE_EL*2)   // bytes per stage = 24576

// ---------------------------------------------------------------------------
// QKV projection: double-buffered fp16-split tensor-core GEMM (3-term).
// ---------------------------------------------------------------------------
__global__ __launch_bounds__(256) void qkv_proj_kernel(
    const float* __restrict__ xq, const float* __restrict__ xk, const float* __restrict__ xv,
    const float* __restrict__ Wq, const float* __restrict__ bq,
    const float* __restrict__ Wk, const float* __restrict__ bk,
    const float* __restrict__ Wv, const float* __restrict__ bv)
{
    int z = blockIdx.z;
    const float* X    = (z == 0) ? xq : (z == 1) ? xk : xv;
    const float* W    = (z == 0) ? Wq : (z == 1) ? Wk : Wv;
    const float* bias = (z == 0) ? bq : (z == 1) ? bk : bv;
    float* out        = (z == 0) ? g_q : (z == 1) ? g_k : g_v;

    __shared__ __align__(16) __half sm[2*G_STAGE_EL];   // 48 KB

    int tid  = threadIdx.x;
    int lane = tid & 31;
    int wid  = tid >> 5;
    int wm   = wid & 1;
    int wn   = wid >> 1;
    int m0 = blockIdx.y * 128;
    int n0 = blockIdx.x * 128;

    int grow = tid >> 1;
    int gk8  = (tid & 1) * 8;
    const float* Abase = X + (size_t)(m0 + grow) * DM + gk8;
    const float* Bbase = W + (size_t)(n0 + grow) * DM + gk8;
    __half* sa_hi = sm + T_A_HI + grow * LDAB + gk8;
    __half* sa_lo = sm + T_A_LO + grow * LDAB + gk8;
    __half* sb_hi = sm + T_B_HI + grow * LDAB + gk8;
    __half* sb_lo = sm + T_B_LO + grow * LDAB + gk8;

    uint32_t smem_u32 = (uint32_t)__cvta_generic_to_shared(sm);
    int a_row = lane & 15, a_kh = (lane >> 4) * 8;
    uint32_t adA[4], adAlo[4];
    #pragma unroll
    for (int mt = 0; mt < 4; mt++) {
        int r = wm * 64 + mt * 16 + a_row;
        adA[mt]   = smem_u32 + (uint32_t)(T_A_HI + r * LDAB + a_kh) * 2;
        adAlo[mt] = smem_u32 + (uint32_t)(T_A_LO + r * LDAB + a_kh) * 2;
    }
    int b_nrow = ((lane >> 4) & 1) * 8 + (lane & 7);
    int b_k    = ((lane >> 3) & 1) * 8;
    uint32_t adB[2], adBlo[2];
    #pragma unroll
    for (int p = 0; p < 2; p++) {
        int r = wn * 32 + p * 16 + b_nrow;
        adB[p]   = smem_u32 + (uint32_t)(T_B_HI + r * LDAB + b_k) * 2;
        adBlo[p] = smem_u32 + (uint32_t)(T_B_LO + r * LDAB + b_k) * 2;
    }

    float C[4][4][4] = {};

    float4 a0 = *(const float4*)(Abase + 0);
    float4 a1 = *(const float4*)(Abase + 4);
    float4 b0 = *(const float4*)(Bbase + 0);
    float4 b1 = *(const float4*)(Bbase + 4);

    split_store_h(a0, a1, sa_hi, sa_lo);
    split_store_h(b0, b1, sb_hi, sb_lo);
    __syncthreads();

    uint32_t curB = 0;
    int      curE = 0;

    for (int k0 = 0; k0 < DM; k0 += 16) {
        bool more = (k0 + 16) < DM;
        if (more) {
            a0 = *(const float4*)(Abase + k0 + 16);
            a1 = *(const float4*)(Abase + k0 + 20);
            b0 = *(const float4*)(Bbase + k0 + 16);
            b1 = *(const float4*)(Bbase + k0 + 20);
        }

        uint32_t A[4][4], Bh[4][2], Bl[4][2];
        #pragma unroll
        for (int mt = 0; mt < 4; mt++)
            ldsm_x4(A[mt][0], A[mt][1], A[mt][2], A[mt][3], adA[mt] + curB);
        #pragma unroll
        for (int p = 0; p < 2; p++) {
            uint32_t r0, r1, r2, r3;
            ldsm_x4(r0, r1, r2, r3, adB[p] + curB);
            Bh[p*2+0][0] = r0; Bh[p*2+0][1] = r1;
            Bh[p*2+1][0] = r2; Bh[p*2+1][1] = r3;
            ldsm_x4(r0, r1, r2, r3, adBlo[p] + curB);
            Bl[p*2+0][0] = r0; Bl[p*2+0][1] = r1;
            Bl[p*2+1][0] = r2; Bl[p*2+1][1] = r3;
        }
        #pragma unroll
        for (int mt = 0; mt < 4; mt++)
            #pragma unroll
            for (int nt = 0; nt < 4; nt++) {
                mma_f16(C[mt][nt], A[mt], Bh[nt]);
                mma_f16(C[mt][nt], A[mt], Bl[nt]);
            }
        #pragma unroll
        for (int mt = 0; mt < 4; mt++)
            ldsm_x4(A[mt][0], A[mt][1], A[mt][2], A[mt][3], adAlo[mt] + curB);
        #pragma unroll
        for (int mt = 0; mt < 4; mt++)
            #pragma unroll
            for (int nt = 0; nt < 4; nt++)
                mma_f16(C[mt][nt], A[mt], Bh[nt]);

        if (more) {
            int nx = curE ^ G_STAGE_EL;
            split_store_h(a0, a1, sa_hi + nx, sa_lo + nx);
            split_store_h(b0, b1, sb_hi + nx, sb_lo + nx);
        }
        __syncthreads();
        curB ^= G_STAGE_B;
        curE ^= G_STAGE_EL;
    }

    int crow = lane >> 2;
    int ccol = (lane & 3) * 2;
    #pragma unroll
    for (int nt = 0; nt < 4; nt++) {
        int n = n0 + wn * 32 + nt * 8 + ccol;
        int h = n >> 6, dk = n & 63;
        float bi0 = bias[n], bi1 = bias[n + 1];
        #pragma unroll
        for (int mt = 0; mt < 4; mt++) {
            #pragma unroll
            for (int half = 0; half < 2; half++) {
                int m = m0 + wm * 64 + mt * 16 + crow + half * 8;
                int b_ = m >> 11, s = m & 2047;
                float* op = out + (((size_t)(b_ * NH + h)) * S_LEN + s) * DKH + dk;
                float2 r = make_float2(C[mt][nt][half*2+0] + bi0, C[mt][nt][half*2+1] + bi1);
                *(float2*)op = r;
            }
        }
    }
}

// ---------------------------------------------------------------------------
// Output projection: same fp16-split 3-term double-buffered structure.
// ---------------------------------------------------------------------------
__global__ __launch_bounds__(256) void out_proj_kernel(
    const float* __restrict__ Wo, const float* __restrict__ bo, float* __restrict__ out)
{
    __shared__ __align__(16) __half sm[2*G_STAGE_EL];

    int tid  = threadIdx.x;
    int lane = tid & 31;
    int wid  = tid >> 5;
    int wm   = wid & 1;
    int wn   = wid >> 1;
    int m0 = blockIdx.y * 128;
    int n0 = blockIdx.x * 128;

    int grow = tid >> 1;
    int gk8  = (tid & 1) * 8;
    int m  = m0 + grow;
    int b_ = m >> 11, ss = m & 2047;
    const float* arow = g_attn + ((size_t)b_ * NH) * S_LEN * DKH + (size_t)ss * DKH;
    const float* Bbase = Wo + (size_t)(n0 + grow) * DM + gk8;
    __half* sa_hi = sm + T_A_HI + grow * LDAB + gk8;
    __half* sa_lo = sm + T_A_LO + grow * LDAB + gk8;
    __half* sb_hi = sm + T_B_HI + grow * LDAB + gk8;
    __half* sb_lo = sm + T_B_LO + grow * LDAB + gk8;

    auto lda = [&](int k) -> float4 {
        return *(const float4*)(arow + (size_t)(k >> 6) * (S_LEN * DKH) + (k & 63));
    };

    uint32_t smem_u32 = (uint32_t)__cvta_generic_to_shared(sm);
    int a_row = lane & 15, a_kh = (lane >> 4) * 8;
    uint32_t adA[4], adAlo[4];
    #pragma unroll
    for (int mt = 0; mt < 4; mt++) {
        int r = wm * 64 + mt * 16 + a_row;
        adA[mt]   = smem_u32 + (uint32_t)(T_A_HI + r * LDAB + a_kh) * 2;
        adAlo[mt] = smem_u32 + (uint32_t)(T_A_LO + r * LDAB + a_kh) * 2;
    }
    int b_nrow = ((lane >> 4) & 1) * 8 + (lane & 7);
    int b_k    = ((lane >> 3) & 1) * 8;
    uint32_t adB[2], adBlo[2];
    #pragma unroll
    for (int p = 0; p < 2; p++) {
        int r = wn * 32 + p * 16 + b_nrow;
        adB[p]   = smem_u32 + (uint32_t)(T_B_HI + r * LDAB + b_k) * 2;
        adBlo[p] = smem_u32 + (uint32_t)(T_B_LO + r * LDAB + b_k) * 2;
    }

    float C[4][4][4] = {};

    float4 a0 = lda(gk8);
    float4 a1 = lda(gk8 + 4);
    float4 b0 = *(const float4*)(Bbase + 0);
    float4 b1 = *(const float4*)(Bbase + 4);

    split_store_h(a0, a1, sa_hi, sa_lo);
    split_store_h(b0, b1, sb_hi, sb_lo);
    __syncthreads();

    uint32_t curB = 0;
    int      curE = 0;

    for (int k0 = 0; k0 < DM; k0 += 16) {
        bool more = (k0 + 16) < DM;
        if (more) {
            a0 = lda(k0 + 16 + gk8);
            a1 = lda(k0 + 16 + gk8 + 4);
            b0 = *(const float4*)(Bbase + k0 + 16);
            b1 = *(const float4*)(Bbase + k0 + 20);
        }

        uint32_t A[4][4], Bh[4][2], Bl[4][2];
        #pragma unroll
        for (int mt = 0; mt < 4; mt++)
            ldsm_x4(A[mt][0], A[mt][1], A[mt][2], A[mt][3], adA[mt] + curB);
        #pragma unroll
        for (int p = 0; p < 2; p++) {
            uint32_t r0, r1, r2, r3;
            ldsm_x4(r0, r1, r2, r3, adB[p] + curB);
            Bh[p*2+0][0] = r0; Bh[p*2+0][1] = r1;
            Bh[p*2+1][0] = r2; Bh[p*2+1][1] = r3;
            ldsm_x4(r0, r1, r2, r3, adBlo[p] + curB);
            Bl[p*2+0][0] = r0; Bl[p*2+0][1] = r1;
            Bl[p*2+1][0] = r2; Bl[p*2+1][1] = r3;
        }
        #pragma unroll
        for (int mt = 0; mt < 4; mt++)
            #pragma unroll
            for (int nt = 0; nt < 4; nt++) {
                mma_f16(C[mt][nt], A[mt], Bh[nt]);
                mma_f16(C[mt][nt], A[mt], Bl[nt]);
            }
        #pragma unroll
        for (int mt = 0; mt < 4; mt++)
            ldsm_x4(A[mt][0], A[mt][1], A[mt][2], A[mt][3], adAlo[mt] + curB);
        #pragma unroll
        for (int mt = 0; mt < 4; mt++)
            #pragma unroll
            for (int nt = 0; nt < 4; nt++)
                mma_f16(C[mt][nt], A[mt], Bh[nt]);

        if (more) {
            int nx = curE ^ G_STAGE_EL;
            split_store_h(a0, a1, sa_hi + nx, sa_lo + nx);
            split_store_h(b0, b1, sb_hi + nx, sb_lo + nx);
        }
        __syncthreads();
        curB ^= G_STAGE_B;
        curE ^= G_STAGE_EL;
    }

    int crow = lane >> 2;
    int ccol = (lane & 3) * 2;
    #pragma unroll
    for (int nt = 0; nt < 4; nt++) {
        int n = n0 + wn * 32 + nt * 8 + ccol;
        float bi0 = bo[n], bi1 = bo[n + 1];
        #pragma unroll
        for (int mt = 0; mt < 4; mt++) {
            #pragma unroll
            for (int half = 0; half < 2; half++) {
                int mr = m0 + wm * 64 + mt * 16 + crow + half * 8;
                float2 r = make_float2(C[mt][nt][half*2+0] + bi0, C[mt][nt][half*2+1] + bi1);
                *(float2*)(out + (size_t)mr * DM + n) = r;
            }
        }
    }
}

// ---------------------------------------------------------------------------
// Flash attention, fp16 pipeline: QK = Qh*(Kh+Kl) [2 MMA], PV = P*(Vh+Vl) [2 MMA].
// CTA: 128 q rows x one (b,h); 8 warps x 16 q rows; kv tiles of 64, 2-stage.
// ---------------------------------------------------------------------------
#define LDK 72
#define A_STAGE_EL (256*LDK)
#define A_STAGE_B  (A_STAGE_EL*2)   // 36864 bytes

extern __shared__ __half dsm[];

__global__ __launch_bounds__(256) void attn_kernel(const int* __restrict__ mask)
{
    const float MSCALE = 0.125f * 1.44269504f;   // (1/8) * log2(e)
    const float MNEG   = -1.442695e9f;           // -1e9 * log2(e)

    int tid  = threadIdx.x;
    int lane = tid & 31;
    int warp = tid >> 5;
    int bh = blockIdx.y;
    int b  = bh >> 4;
    int q0 = blockIdx.x * 128;

    const float* Qg = g_q + (size_t)bh * S_LEN * DKH;
    const float* Kg = g_k + (size_t)bh * S_LEN * DKH;
    const float* Vg = g_v + (size_t)bh * S_LEN * DKH;

    uint32_t base = (uint32_t)__cvta_generic_to_shared(dsm);

    // ---- stage Q (single fp16) into stage0 rows 0-127 ----
    {
        int row = tid >> 1;
        int c0 = (tid & 1) * 32;
        const float* src = Qg + (size_t)(q0 + row) * DKH + c0;
        #pragma unroll
        for (int c = 0; c < 32; c += 8) {
            float4 u0 = *(const float4*)(src + c);
            float4 u1 = *(const float4*)(src + c + 4);
            cvt_store_h(u0, u1, dsm + row*LDK + c0 + c);
        }
    }
    __syncthreads();

    // ---- Q A-fragments (resident all kernel) ----
    uint32_t Qh[4][4];
    {
        int a_row = lane & 15, a_kh = (lane >> 4) * 8;
        #pragma unroll
        for (int kt = 0; kt < 4; kt++) {
            uint32_t off = (uint32_t)((warp*16 + a_row)*LDK + kt*16 + a_kh) * 2;
            ldsm_x4(Qh[kt][0], Qh[kt][1], Qh[kt][2], Qh[kt][3], base + off);
        }
    }
    __syncthreads();   // done reading Q staging before overwriting stage0

    // ---- stage kv tile 0 into stage0 ----
    int row4 = tid >> 2;           // 0..63
    int c04  = (tid & 3) * 16;     // 0,16,32,48
    {
        const float* ks = Kg + (size_t)row4 * DKH + c04;
        const float* vs = Vg + (size_t)row4 * DKH + c04;
        #pragma unroll
        for (int c = 0; c < 16; c += 8) {
            float4 u0 = *(const float4*)(ks + c);
            float4 u1 = *(const float4*)(ks + c + 4);
            split_store_h(u0, u1, dsm + row4*LDK + c04 + c, dsm + (64+row4)*LDK + c04 + c);
            float4 w0 = *(const float4*)(vs + c);
            float4 w1 = *(const float4*)(vs + c + 4);
            split_store_h(w0, w1, dsm + (128+row4)*LDK + c04 + c, dsm + (192+row4)*LDK + c04 + c);
        }
    }
    __syncthreads();

    float m_i[2] = {-1e30f, -1e30f};
    float l_i[2] = {0.f, 0.f};
    float O[8][4] = {};

    int r0 = lane >> 2;
    int c2 = (lane & 3) * 2;
    int b_nrow = ((lane >> 4) & 1) * 8 + (lane & 7);
    int b_k    = ((lane >> 3) & 1) * 8;
    int v_row  = ((lane >> 3) & 1) * 8 + (lane & 7);
    int v_col  = (lane >> 4) * 8;

    const float* ksp = Kg + (size_t)row4 * DKH + c04;
    const float* vsp = Vg + (size_t)row4 * DKH + c04;

    for (int it = 0; it < S_LEN/64; it++) {
        int cur = it & 1;
        uint32_t sb = base + (uint32_t)cur * A_STAGE_B;
        bool more = it + 1 < S_LEN/64;

        // ---- prefetch next kv tile into registers ----
        float4 pk0, pk1, pk2, pk3, pv0, pv1, pv2, pv3;
        if (more) {
            const float* ks = ksp + (size_t)(it+1) * 64 * DKH;
            const float* vs = vsp + (size_t)(it+1) * 64 * DKH;
            pk0 = *(const float4*)(ks + 0);  pk1 = *(const float4*)(ks + 4);
            pk2 = *(const float4*)(ks + 8);  pk3 = *(const float4*)(ks + 12);
            pv0 = *(const float4*)(vs + 0);  pv1 = *(const float4*)(vs + 4);
            pv2 = *(const float4*)(vs + 8);  pv3 = *(const float4*)(vs + 12);
        }

        // ---- mask loads issued early (hidden behind QK MMAs) ----
        int k0 = it * 64;
        const int* mrow0 = mask + ((size_t)b * S_LEN + q0 + warp*16 + r0) * S_LEN + k0 + c2;
        const int* mrow1 = mrow0 + 8 * S_LEN;
        int2 mreg0[8], mreg1[8];
        #pragma unroll
        for (int nt = 0; nt < 8; nt++) {
            mreg0[nt] = *(const int2*)(mrow0 + nt*8);
            mreg1[nt] = *(const int2*)(mrow1 + nt*8);
        }

        // ---- S = Q K^T (2-term fp16) ----
        float S[8][4] = {};
        #pragma unroll
        for (int kt = 0; kt < 4; kt++) {
            uint32_t Bh[8][2], Bl[8][2];
            #pragma unroll
            for (int np = 0; np < 4; np++) {
                uint32_t x0, x1, x2, x3;
                uint32_t off = sb + (uint32_t)((np*16 + b_nrow)*LDK + kt*16 + b_k) * 2;
                ldsm_x4(x0, x1, x2, x3, off);
                Bh[np*2+0][0] = x0; Bh[np*2+0][1] = x1;
                Bh[np*2+1][0] = x2; Bh[np*2+1][1] = x3;
                ldsm_x4(x0, x1, x2, x3, off + 64*LDK*2);
                Bl[np*2+0][0] = x0; Bl[np*2+0][1] = x1;
                Bl[np*2+1][0] = x2; Bl[np*2+1][1] = x3;
            }
            #pragma unroll
            for (int nt = 0; nt < 8; nt++) {
                mma_f16(S[nt], Qh[kt], Bh[nt]);
                mma_f16(S[nt], Qh[kt], Bl[nt]);
            }
        }

        // ---- mask + scale (log2 domain) ----
        #pragma unroll
        for (int nt = 0; nt < 8; nt++) {
            S[nt][0] = mreg0[nt].x ? S[nt][0] * MSCALE : MNEG;
            S[nt][1] = mreg0[nt].y ? S[nt][1] * MSCALE : MNEG;
            S[nt][2] = mreg1[nt].x ? S[nt][2] * MSCALE : MNEG;
            S[nt][3] = mreg1[nt].y ? S[nt][3] * MSCALE : MNEG;
        }

        // ---- online softmax (base-2) ----
        #pragma unroll
        for (int h = 0; h < 2; h++) {
            float mx = -1e30f;
            #pragma unroll
            for (int nt = 0; nt < 8; nt++)
                mx = fmaxf(mx, fmaxf(S[nt][2*h], S[nt][2*h+1]));
            mx = fmaxf(mx, __shfl_xor_sync(0xffffffffu, mx, 1));
            mx = fmaxf(mx, __shfl_xor_sync(0xffffffffu, mx, 2));
            float mnew  = fmaxf(m_i[h], mx);
            float alpha = exp2f(m_i[h] - mnew);
            m_i[h] = mnew;
            float ls = 0.f;
            #pragma unroll
            for (int nt = 0; nt < 8; nt++) {
                S[nt][2*h]   = exp2f(S[nt][2*h]   - mnew);
                S[nt][2*h+1] = exp2f(S[nt][2*h+1] - mnew);
                ls += S[nt][2*h] + S[nt][2*h+1];
            }
            ls += __shfl_xor_sync(0xffffffffu, ls, 1);
            ls += __shfl_xor_sync(0xffffffffu, ls, 2);
            l_i[h] = l_i[h] * alpha + ls;
            #pragma unroll
            for (int nt = 0; nt < 8; nt++) { O[nt][2*h] *= alpha; O[nt][2*h+1] *= alpha; }
        }

        // ---- O += P V (P single fp16, V hi/lo) ----
        #pragma unroll
        for (int kt = 0; kt < 4; kt++) {
            uint32_t Ah[4];
            Ah[0] = pack_h(S[2*kt+0][0], S[2*kt+0][1]);
            Ah[1] = pack_h(S[2*kt+0][2], S[2*kt+0][3]);
            Ah[2] = pack_h(S[2*kt+1][0], S[2*kt+1][1]);
            Ah[3] = pack_h(S[2*kt+1][2], S[2*kt+1][3]);

            uint32_t Vh[8][2], Vl[8][2];
            #pragma unroll
            for (int np = 0; np < 4; np++) {
                uint32_t x0, x1, x2, x3;
                uint32_t off = sb + 128*LDK*2 + (uint32_t)((kt*16 + v_row)*LDK + np*16 + v_col) * 2;
                ldsm_x4_t(x0, x1, x2, x3, off);
                Vh[np*2+0][0] = x0; Vh[np*2+0][1] = x1;
                Vh[np*2+1][0] = x2; Vh[np*2+1][1] = x3;
                ldsm_x4_t(x0, x1, x2, x3, off + 64*LDK*2);
                Vl[np*2+0][0] = x0; Vl[np*2+0][1] = x1;
                Vl[np*2+1][0] = x2; Vl[np*2+1][1] = x3;
            }
            #pragma unroll
            for (int nt = 0; nt < 8; nt++) {
                mma_f16(O[nt], Ah, Vh[nt]);
                mma_f16(O[nt], Ah, Vl[nt]);
            }
        }

        // ---- store prefetched tile into the other stage ----
        if (more) {
            __half* nx = dsm + (cur ^ 1) * A_STAGE_EL;
            split_store_h(pk0, pk1, nx + row4*LDK + c04,     nx + (64+row4)*LDK + c04);
            split_store_h(pk2, pk3, nx + row4*LDK + c04 + 8, nx + (64+row4)*LDK + c04 + 8);
            split_store_h(pv0, pv1, nx + (128+row4)*LDK + c04,     nx + (192+row4)*LDK + c04);
            split_store_h(pv2, pv3, nx + (128+row4)*LDK + c04 + 8, nx + (192+row4)*LDK + c04 + 8);
        }
        __syncthreads();
    }

    // ---- finalize ----
    float inv0 = 1.0f / l_i[0];
    float inv1 = 1.0f / l_i[1];
    float* orow0 = g_attn + ((size_t)bh * S_LEN + q0 + warp*16 + r0) * DKH + c2;
    float* orow1 = orow0 + 8 * DKH;
    #pragma unroll
    for (int nt = 0; nt < 8; nt++) {
        *(float2*)(orow0 + nt*8) = make_float2(O[nt][0] * inv0, O[nt][1] * inv0);
        *(float2*)(orow1 + nt*8) = make_float2(O[nt][2] * inv1, O[nt][3] * inv1);
    }
}

extern "C" void kernel_launch(void* const* d_in, const int* in_sizes, int n_in,
                              void* d_out, int out_size)
{
    const float* query = (const float*)d_in[0];
    const float* key_  = (const float*)d_in[1];
    const float* value = (const float*)d_in[2];
    const int*   mask  = (const int*)d_in[3];
    const float* Wq = (const float*)d_in[4];
    const float* bq = (const float*)d_in[5];
    const float* Wk = (const float*)d_in[6];
    const float* bk = (const float*)d_in[7];
    const float* Wv = (const float*)d_in[8];
    const float* bv = (const float*)d_in[9];
    const float* Wo = (const float*)d_in[10];
    const float* bo = (const float*)d_in[11];
    float* out = (float*)d_out;

    cudaFuncSetAttribute(attn_kernel, cudaFuncAttributeMaxDynamicSharedMemorySize,
                         2 * A_STAGE_B);

    dim3 g1(DM / 128, (BB * S_LEN) / 128, 3);
    qkv_proj_kernel<<<g1, 256>>>(query, key_, value, Wq, bq, Wk, bk, Wv, bv);

    dim3 g2(S_LEN / 128, BB * NH);
    attn_kernel<<<g2, 256, 2 * A_STAGE_B>>>(mask);

    dim3 g3(DM / 128, (BB * S_LEN) / 128);
    out_proj_kernel<<<g3, 256>>>(Wo, bo, out);
}

// round 9
// speedup vs baseline: 2.7013x; 1.0756x over previous
#include <cuda_runtime.h>
#include <cuda_fp16.h>
#include <cstdint>

#define S_LEN 2048
#define DM    1024
#define NH    16
#define DKH   64
#define BB    2

// scratch: [B,H,S,DK] layouts
__device__ float g_q[BB*NH*S_LEN*DKH];
__device__ float g_k[BB*NH*S_LEN*DKH];
__device__ float g_v[BB*NH*S_LEN*DKH];
__device__ float g_attn[BB*NH*S_LEN*DKH];

// ---------------------------------------------------------------------------
// MMA helpers (warp-level, fp16 in / f32 out)
// ---------------------------------------------------------------------------
__device__ __forceinline__ void ldsm_x4(uint32_t& r0, uint32_t& r1, uint32_t& r2, uint32_t& r3,
                                        uint32_t addr) {
    asm volatile("ldmatrix.sync.aligned.m8n8.x4.shared.b16 {%0,%1,%2,%3}, [%4];"
                 : "=r"(r0), "=r"(r1), "=r"(r2), "=r"(r3) : "r"(addr));
}

__device__ __forceinline__ void ldsm_x4_t(uint32_t& r0, uint32_t& r1, uint32_t& r2, uint32_t& r3,
                                          uint32_t addr) {
    asm volatile("ldmatrix.sync.aligned.m8n8.x4.trans.shared.b16 {%0,%1,%2,%3}, [%4];"
                 : "=r"(r0), "=r"(r1), "=r"(r2), "=r"(r3) : "r"(addr));
}

__device__ __forceinline__ void mma_f16(float* c, const uint32_t* a, const uint32_t* b) {
    asm volatile(
        "mma.sync.aligned.m16n8k16.row.col.f32.f16.f16.f32 "
        "{%0,%1,%2,%3}, {%4,%5,%6,%7}, {%8,%9}, {%0,%1,%2,%3};"
        : "+f"(c[0]), "+f"(c[1]), "+f"(c[2]), "+f"(c[3])
        : "r"(a[0]), "r"(a[1]), "r"(a[2]), "r"(a[3]), "r"(b[0]), "r"(b[1]));
}

// split 8 floats into fp16 hi/lo and store 16B each
__device__ __forceinline__ void split_store_h(float4 u0, float4 u1,
                                              __half* dst_hi, __half* dst_lo) {
    float x[8] = {u0.x, u0.y, u0.z, u0.w, u1.x, u1.y, u1.z, u1.w};
    __half2 h[4], l[4];
    #pragma unroll
    for (int i = 0; i < 4; i++) {
        float a = x[2*i], b = x[2*i+1];
        __half ha = __float2half_rn(a);
        __half hb = __float2half_rn(b);
        __half la = __float2half_rn(a - __half2float(ha));
        __half lb = __float2half_rn(b - __half2float(hb));
        h[i] = __halves2half2(ha, hb);
        l[i] = __halves2half2(la, lb);
    }
    *(uint4*)dst_hi = *(uint4*)h;
    *(uint4*)dst_lo = *(uint4*)l;
}

// convert 8 floats to single fp16, store 16B
__device__ __forceinline__ void cvt_store_h(float4 u0, float4 u1, __half* dst) {
    __half2 h[4];
    h[0] = __floats2half2_rn(u0.x, u0.y);
    h[1] = __floats2half2_rn(u0.z, u0.w);
    h[2] = __floats2half2_rn(u1.x, u1.y);
    h[3] = __floats2half2_rn(u1.z, u1.w);
    *(uint4*)dst = *(uint4*)h;
}

__device__ __forceinline__ uint32_t pack_h(float a, float b) {
    __half2 t = __floats2half2_rn(a, b);
    return *(uint32_t*)&t;
}

// smem layout constants for the GEMM kernels
#define LDAB 24                 // fp16 per row (16 data + 8 pad)
#define T_A_HI 0
#define T_A_LO (128*LDAB)
#define T_B_HI (2*128*LDAB)
#define T_B_LO (3*128*LDAB)
#define G_STAGE_EL (4*128*LDAB)     // elements per stage = 12288
#define G_STAGE_B  (G_STAGE_EL*2)   // bytes per stage = 24576

// ---------------------------------------------------------------------------
// QKV projection: double-buffered fp16-split tensor-core GEMM (3-term).
// __launch_bounds__(256,2): cap regs at 128 so 2 CTAs/SM fit (R8 regression fix).
// ---------------------------------------------------------------------------
__global__ __launch_bounds__(256, 2) void qkv_proj_kernel(
    const float* __restrict__ xq, const float* __restrict__ xk, const float* __restrict__ xv,
    const float* __restrict__ Wq, const float* __restrict__ bq,
    const float* __restrict__ Wk, const float* __restrict__ bk,
    const float* __restrict__ Wv, const float* __restrict__ bv)
{
    int z = blockIdx.z;
    const float* X    = (z == 0) ? xq : (z == 1) ? xk : xv;
    const float* W    = (z == 0) ? Wq : (z == 1) ? Wk : Wv;
    const float* bias = (z == 0) ? bq : (z == 1) ? bk : bv;
    float* out        = (z == 0) ? g_q : (z == 1) ? g_k : g_v;

    __shared__ __align__(16) __half sm[2*G_STAGE_EL];   // 48 KB

    int tid  = threadIdx.x;
    int lane = tid & 31;
    int wid  = tid >> 5;
    int wm   = wid & 1;
    int wn   = wid >> 1;
    int m0 = blockIdx.y * 128;
    int n0 = blockIdx.x * 128;

    int grow = tid >> 1;
    int gk8  = (tid & 1) * 8;
    const float* Abase = X + (size_t)(m0 + grow) * DM + gk8;
    const float* Bbase = W + (size_t)(n0 + grow) * DM + gk8;
    __half* sa_hi = sm + T_A_HI + grow * LDAB + gk8;
    __half* sa_lo = sm + T_A_LO + grow * LDAB + gk8;
    __half* sb_hi = sm + T_B_HI + grow * LDAB + gk8;
    __half* sb_lo = sm + T_B_LO + grow * LDAB + gk8;

    uint32_t smem_u32 = (uint32_t)__cvta_generic_to_shared(sm);
    int a_row = lane & 15, a_kh = (lane >> 4) * 8;
    uint32_t adA[4], adAlo[4];
    #pragma unroll
    for (int mt = 0; mt < 4; mt++) {
        int r = wm * 64 + mt * 16 + a_row;
        adA[mt]   = smem_u32 + (uint32_t)(T_A_HI + r * LDAB + a_kh) * 2;
        adAlo[mt] = smem_u32 + (uint32_t)(T_A_LO + r * LDAB + a_kh) * 2;
    }
    int b_nrow = ((lane >> 4) & 1) * 8 + (lane & 7);
    int b_k    = ((lane >> 3) & 1) * 8;
    uint32_t adB[2], adBlo[2];
    #pragma unroll
    for (int p = 0; p < 2; p++) {
        int r = wn * 32 + p * 16 + b_nrow;
        adB[p]   = smem_u32 + (uint32_t)(T_B_HI + r * LDAB + b_k) * 2;
        adBlo[p] = smem_u32 + (uint32_t)(T_B_LO + r * LDAB + b_k) * 2;
    }

    float C[4][4][4] = {};

    float4 a0 = *(const float4*)(Abase + 0);
    float4 a1 = *(const float4*)(Abase + 4);
    float4 b0 = *(const float4*)(Bbase + 0);
    float4 b1 = *(const float4*)(Bbase + 4);

    split_store_h(a0, a1, sa_hi, sa_lo);
    split_store_h(b0, b1, sb_hi, sb_lo);
    __syncthreads();

    uint32_t curB = 0;
    int      curE = 0;

    for (int k0 = 0; k0 < DM; k0 += 16) {
        bool more = (k0 + 16) < DM;
        if (more) {
            a0 = *(const float4*)(Abase + k0 + 16);
            a1 = *(const float4*)(Abase + k0 + 20);
            b0 = *(const float4*)(Bbase + k0 + 16);
            b1 = *(const float4*)(Bbase + k0 + 20);
        }

        uint32_t A[4][4], Bh[4][2], Bl[4][2];
        #pragma unroll
        for (int mt = 0; mt < 4; mt++)
            ldsm_x4(A[mt][0], A[mt][1], A[mt][2], A[mt][3], adA[mt] + curB);
        #pragma unroll
        for (int p = 0; p < 2; p++) {
            uint32_t r0, r1, r2, r3;
            ldsm_x4(r0, r1, r2, r3, adB[p] + curB);
            Bh[p*2+0][0] = r0; Bh[p*2+0][1] = r1;
            Bh[p*2+1][0] = r2; Bh[p*2+1][1] = r3;
            ldsm_x4(r0, r1, r2, r3, adBlo[p] + curB);
            Bl[p*2+0][0] = r0; Bl[p*2+0][1] = r1;
            Bl[p*2+1][0] = r2; Bl[p*2+1][1] = r3;
        }
        #pragma unroll
        for (int mt = 0; mt < 4; mt++)
            #pragma unroll
            for (int nt = 0; nt < 4; nt++) {
                mma_f16(C[mt][nt], A[mt], Bh[nt]);
                mma_f16(C[mt][nt], A[mt], Bl[nt]);
            }
        #pragma unroll
        for (int mt = 0; mt < 4; mt++)
            ldsm_x4(A[mt][0], A[mt][1], A[mt][2], A[mt][3], adAlo[mt] + curB);
        #pragma unroll
        for (int mt = 0; mt < 4; mt++)
            #pragma unroll
            for (int nt = 0; nt < 4; nt++)
                mma_f16(C[mt][nt], A[mt], Bh[nt]);

        if (more) {
            int nx = curE ^ G_STAGE_EL;
            split_store_h(a0, a1, sa_hi + nx, sa_lo + nx);
            split_store_h(b0, b1, sb_hi + nx, sb_lo + nx);
        }
        __syncthreads();
        curB ^= G_STAGE_B;
        curE ^= G_STAGE_EL;
    }

    int crow = lane >> 2;
    int ccol = (lane & 3) * 2;
    #pragma unroll
    for (int nt = 0; nt < 4; nt++) {
        int n = n0 + wn * 32 + nt * 8 + ccol;
        int h = n >> 6, dk = n & 63;
        float bi0 = bias[n], bi1 = bias[n + 1];
        #pragma unroll
        for (int mt = 0; mt < 4; mt++) {
            #pragma unroll
            for (int half = 0; half < 2; half++) {
                int m = m0 + wm * 64 + mt * 16 + crow + half * 8;
                int b_ = m >> 11, s = m & 2047;
                float* op = out + (((size_t)(b_ * NH + h)) * S_LEN + s) * DKH + dk;
                float2 r = make_float2(C[mt][nt][half*2+0] + bi0, C[mt][nt][half*2+1] + bi1);
                *(float2*)op = r;
            }
        }
    }
}

// ---------------------------------------------------------------------------
// Output projection: same fp16-split 3-term double-buffered structure.
// ---------------------------------------------------------------------------
__global__ __launch_bounds__(256, 2) void out_proj_kernel(
    const float* __restrict__ Wo, const float* __restrict__ bo, float* __restrict__ out)
{
    __shared__ __align__(16) __half sm[2*G_STAGE_EL];

    int tid  = threadIdx.x;
    int lane = tid & 31;
    int wid  = tid >> 5;
    int wm   = wid & 1;
    int wn   = wid >> 1;
    int m0 = blockIdx.y * 128;
    int n0 = blockIdx.x * 128;

    int grow = tid >> 1;
    int gk8  = (tid & 1) * 8;
    int m  = m0 + grow;
    int b_ = m >> 11, ss = m & 2047;
    const float* arow = g_attn + ((size_t)b_ * NH) * S_LEN * DKH + (size_t)ss * DKH;
    const float* Bbase = Wo + (size_t)(n0 + grow) * DM + gk8;
    __half* sa_hi = sm + T_A_HI + grow * LDAB + gk8;
    __half* sa_lo = sm + T_A_LO + grow * LDAB + gk8;
    __half* sb_hi = sm + T_B_HI + grow * LDAB + gk8;
    __half* sb_lo = sm + T_B_LO + grow * LDAB + gk8;

    auto lda = [&](int k) -> float4 {
        return *(const float4*)(arow + (size_t)(k >> 6) * (S_LEN * DKH) + (k & 63));
    };

    uint32_t smem_u32 = (uint32_t)__cvta_generic_to_shared(sm);
    int a_row = lane & 15, a_kh = (lane >> 4) * 8;
    uint32_t adA[4], adAlo[4];
    #pragma unroll
    for (int mt = 0; mt < 4; mt++) {
        int r = wm * 64 + mt * 16 + a_row;
        adA[mt]   = smem_u32 + (uint32_t)(T_A_HI + r * LDAB + a_kh) * 2;
        adAlo[mt] = smem_u32 + (uint32_t)(T_A_LO + r * LDAB + a_kh) * 2;
    }
    int b_nrow = ((lane >> 4) & 1) * 8 + (lane & 7);
    int b_k    = ((lane >> 3) & 1) * 8;
    uint32_t adB[2], adBlo[2];
    #pragma unroll
    for (int p = 0; p < 2; p++) {
        int r = wn * 32 + p * 16 + b_nrow;
        adB[p]   = smem_u32 + (uint32_t)(T_B_HI + r * LDAB + b_k) * 2;
        adBlo[p] = smem_u32 + (uint32_t)(T_B_LO + r * LDAB + b_k) * 2;
    }

    float C[4][4][4] = {};

    float4 a0 = lda(gk8);
    float4 a1 = lda(gk8 + 4);
    float4 b0 = *(const float4*)(Bbase + 0);
    float4 b1 = *(const float4*)(Bbase + 4);

    split_store_h(a0, a1, sa_hi, sa_lo);
    split_store_h(b0, b1, sb_hi, sb_lo);
    __syncthreads();

    uint32_t curB = 0;
    int      curE = 0;

    for (int k0 = 0; k0 < DM; k0 += 16) {
        bool more = (k0 + 16) < DM;
        if (more) {
            a0 = lda(k0 + 16 + gk8);
            a1 = lda(k0 + 16 + gk8 + 4);
            b0 = *(const float4*)(Bbase + k0 + 16);
            b1 = *(const float4*)(Bbase + k0 + 20);
        }

        uint32_t A[4][4], Bh[4][2], Bl[4][2];
        #pragma unroll
        for (int mt = 0; mt < 4; mt++)
            ldsm_x4(A[mt][0], A[mt][1], A[mt][2], A[mt][3], adA[mt] + curB);
        #pragma unroll
        for (int p = 0; p < 2; p++) {
            uint32_t r0, r1, r2, r3;
            ldsm_x4(r0, r1, r2, r3, adB[p] + curB);
            Bh[p*2+0][0] = r0; Bh[p*2+0][1] = r1;
            Bh[p*2+1][0] = r2; Bh[p*2+1][1] = r3;
            ldsm_x4(r0, r1, r2, r3, adBlo[p] + curB);
            Bl[p*2+0][0] = r0; Bl[p*2+0][1] = r1;
            Bl[p*2+1][0] = r2; Bl[p*2+1][1] = r3;
        }
        #pragma unroll
        for (int mt = 0; mt < 4; mt++)
            #pragma unroll
            for (int nt = 0; nt < 4; nt++) {
                mma_f16(C[mt][nt], A[mt], Bh[nt]);
                mma_f16(C[mt][nt], A[mt], Bl[nt]);
            }
        #pragma unroll
        for (int mt = 0; mt < 4; mt++)
            ldsm_x4(A[mt][0], A[mt][1], A[mt][2], A[mt][3], adAlo[mt] + curB);
        #pragma unroll
        for (int mt = 0; mt < 4; mt++)
            #pragma unroll
            for (int nt = 0; nt < 4; nt++)
                mma_f16(C[mt][nt], A[mt], Bh[nt]);

        if (more) {
            int nx = curE ^ G_STAGE_EL;
            split_store_h(a0, a1, sa_hi + nx, sa_lo + nx);
            split_store_h(b0, b1, sb_hi + nx, sb_lo + nx);
        }
        __syncthreads();
        curB ^= G_STAGE_B;
        curE ^= G_STAGE_EL;
    }

    int crow = lane >> 2;
    int ccol = (lane & 3) * 2;
    #pragma unroll
    for (int nt = 0; nt < 4; nt++) {
        int n = n0 + wn * 32 + nt * 8 + ccol;
        float bi0 = bo[n], bi1 = bo[n + 1];
        #pragma unroll
        for (int mt = 0; mt < 4; mt++) {
            #pragma unroll
            for (int half = 0; half < 2; half++) {
                int mr = m0 + wm * 64 + mt * 16 + crow + half * 8;
                float2 r = make_float2(C[mt][nt][half*2+0] + bi0, C[mt][nt][half*2+1] + bi1);
                *(float2*)(out + (size_t)mr * DM + n) = r;
            }
        }
    }
}

// ---------------------------------------------------------------------------
// Flash attention, fp16: QK = Qh*Kh [1 MMA], PV = P*(Vh+Vl) [2 MMA].
// CTA: 128 q rows x one (b,h); 8 warps x 16 q rows; kv tiles of 64, 2-stage.
// Stage layout (rows of LDK): K single [0-63], V hi [64-127], V lo [128-191].
// ---------------------------------------------------------------------------
#define LDK 72
#define A_STAGE_EL (192*LDK)        // elements per stage = 13824
#define A_STAGE_B  (A_STAGE_EL*2)   // 27648 bytes

extern __shared__ __half dsm[];

__global__ __launch_bounds__(256) void attn_kernel(const int* __restrict__ mask)
{
    const float MSCALE = 0.125f * 1.44269504f;   // (1/8) * log2(e)
    const float MNEG   = -1.442695e9f;           // -1e9 * log2(e)

    int tid  = threadIdx.x;
    int lane = tid & 31;
    int warp = tid >> 5;
    int bh = blockIdx.y;
    int b  = bh >> 4;
    int q0 = blockIdx.x * 128;

    const float* Qg = g_q + (size_t)bh * S_LEN * DKH;
    const float* Kg = g_k + (size_t)bh * S_LEN * DKH;
    const float* Vg = g_v + (size_t)bh * S_LEN * DKH;

    uint32_t base = (uint32_t)__cvta_generic_to_shared(dsm);

    // ---- stage Q (single fp16) into stage0 rows 0-127 ----
    {
        int row = tid >> 1;
        int c0 = (tid & 1) * 32;
        const float* src = Qg + (size_t)(q0 + row) * DKH + c0;
        #pragma unroll
        for (int c = 0; c < 32; c += 8) {
            float4 u0 = *(const float4*)(src + c);
            float4 u1 = *(const float4*)(src + c + 4);
            cvt_store_h(u0, u1, dsm + row*LDK + c0 + c);
        }
    }
    __syncthreads();

    // ---- Q A-fragments (resident all kernel) ----
    uint32_t Qh[4][4];
    {
        int a_row = lane & 15, a_kh = (lane >> 4) * 8;
        #pragma unroll
        for (int kt = 0; kt < 4; kt++) {
            uint32_t off = (uint32_t)((warp*16 + a_row)*LDK + kt*16 + a_kh) * 2;
            ldsm_x4(Qh[kt][0], Qh[kt][1], Qh[kt][2], Qh[kt][3], base + off);
        }
    }
    __syncthreads();   // done reading Q staging before overwriting stage0

    // ---- stage kv tile 0 into stage0 ----
    int row4 = tid >> 2;           // 0..63
    int c04  = (tid & 3) * 16;     // 0,16,32,48
    {
        const float* ks = Kg + (size_t)row4 * DKH + c04;
        const float* vs = Vg + (size_t)row4 * DKH + c04;
        float4 k0_ = *(const float4*)(ks + 0), k1_ = *(const float4*)(ks + 4);
        float4 k2_ = *(const float4*)(ks + 8), k3_ = *(const float4*)(ks + 12);
        cvt_store_h(k0_, k1_, dsm + row4*LDK + c04);
        cvt_store_h(k2_, k3_, dsm + row4*LDK + c04 + 8);
        float4 w0 = *(const float4*)(vs + 0), w1 = *(const float4*)(vs + 4);
        float4 w2 = *(const float4*)(vs + 8), w3 = *(const float4*)(vs + 12);
        split_store_h(w0, w1, dsm + (64+row4)*LDK + c04,     dsm + (128+row4)*LDK + c04);
        split_store_h(w2, w3, dsm + (64+row4)*LDK + c04 + 8, dsm + (128+row4)*LDK + c04 + 8);
    }
    __syncthreads();

    float m_i[2] = {-1e30f, -1e30f};
    float l_i[2] = {0.f, 0.f};
    float O[8][4] = {};

    int r0 = lane >> 2;
    int c2 = (lane & 3) * 2;
    int b_nrow = ((lane >> 4) & 1) * 8 + (lane & 7);
    int b_k    = ((lane >> 3) & 1) * 8;
    int v_row  = ((lane >> 3) & 1) * 8 + (lane & 7);
    int v_col  = (lane >> 4) * 8;

    const float* ksp = Kg + (size_t)row4 * DKH + c04;
    const float* vsp = Vg + (size_t)row4 * DKH + c04;

    for (int it = 0; it < S_LEN/64; it++) {
        int cur = it & 1;
        uint32_t sb = base + (uint32_t)cur * A_STAGE_B;
        bool more = it + 1 < S_LEN/64;

        // ---- prefetch next kv tile into registers ----
        float4 pk0, pk1, pk2, pk3, pv0, pv1, pv2, pv3;
        if (more) {
            const float* ks = ksp + (size_t)(it+1) * 64 * DKH;
            const float* vs = vsp + (size_t)(it+1) * 64 * DKH;
            pk0 = *(const float4*)(ks + 0);  pk1 = *(const float4*)(ks + 4);
            pk2 = *(const float4*)(ks + 8);  pk3 = *(const float4*)(ks + 12);
            pv0 = *(const float4*)(vs + 0);  pv1 = *(const float4*)(vs + 4);
            pv2 = *(const float4*)(vs + 8);  pv3 = *(const float4*)(vs + 12);
        }

        // ---- mask loads issued early (hidden behind QK MMAs) ----
        int k0 = it * 64;
        const int* mrow0 = mask + ((size_t)b * S_LEN + q0 + warp*16 + r0) * S_LEN + k0 + c2;
        const int* mrow1 = mrow0 + 8 * S_LEN;
        int2 mreg0[8], mreg1[8];
        #pragma unroll
        for (int nt = 0; nt < 8; nt++) {
            mreg0[nt] = *(const int2*)(mrow0 + nt*8);
            mreg1[nt] = *(const int2*)(mrow1 + nt*8);
        }

        // ---- S = Q K^T (single-term fp16) ----
        float S[8][4] = {};
        #pragma unroll
        for (int kt = 0; kt < 4; kt++) {
            uint32_t Bh[8][2];
            #pragma unroll
            for (int np = 0; np < 4; np++) {
                uint32_t x0, x1, x2, x3;
                uint32_t off = sb + (uint32_t)((np*16 + b_nrow)*LDK + kt*16 + b_k) * 2;
                ldsm_x4(x0, x1, x2, x3, off);
                Bh[np*2+0][0] = x0; Bh[np*2+0][1] = x1;
                Bh[np*2+1][0] = x2; Bh[np*2+1][1] = x3;
            }
            #pragma unroll
            for (int nt = 0; nt < 8; nt++)
                mma_f16(S[nt], Qh[kt], Bh[nt]);
        }

        // ---- mask + scale (log2 domain) ----
        #pragma unroll
        for (int nt = 0; nt < 8; nt++) {
            S[nt][0] = mreg0[nt].x ? S[nt][0] * MSCALE : MNEG;
            S[nt][1] = mreg0[nt].y ? S[nt][1] * MSCALE : MNEG;
            S[nt][2] = mreg1[nt].x ? S[nt][2] * MSCALE : MNEG;
            S[nt][3] = mreg1[nt].y ? S[nt][3] * MSCALE : MNEG;
        }

        // ---- online softmax (base-2) ----
        #pragma unroll
        for (int h = 0; h < 2; h++) {
            float mx = -1e30f;
            #pragma unroll
            for (int nt = 0; nt < 8; nt++)
                mx = fmaxf(mx, fmaxf(S[nt][2*h], S[nt][2*h+1]));
            mx = fmaxf(mx, __shfl_xor_sync(0xffffffffu, mx, 1));
            mx = fmaxf(mx, __shfl_xor_sync(0xffffffffu, mx, 2));
            float mnew  = fmaxf(m_i[h], mx);
            float alpha = exp2f(m_i[h] - mnew);
            m_i[h] = mnew;
            float ls = 0.f;
            #pragma unroll
            for (int nt = 0; nt < 8; nt++) {
                S[nt][2*h]   = exp2f(S[nt][2*h]   - mnew);
                S[nt][2*h+1] = exp2f(S[nt][2*h+1] - mnew);
                ls += S[nt][2*h] + S[nt][2*h+1];
            }
            ls += __shfl_xor_sync(0xffffffffu, ls, 1);
            ls += __shfl_xor_sync(0xffffffffu, ls, 2);
            l_i[h] = l_i[h] * alpha + ls;
            #pragma unroll
            for (int nt = 0; nt < 8; nt++) { O[nt][2*h] *= alpha; O[nt][2*h+1] *= alpha; }
        }

        // ---- O += P V (P single fp16, V hi/lo) ----
        #pragma unroll
        for (int kt = 0; kt < 4; kt++) {
            uint32_t Ah[4];
            Ah[0] = pack_h(S[2*kt+0][0], S[2*kt+0][1]);
            Ah[1] = pack_h(S[2*kt+0][2], S[2*kt+0][3]);
            Ah[2] = pack_h(S[2*kt+1][0], S[2*kt+1][1]);
            Ah[3] = pack_h(S[2*kt+1][2], S[2*kt+1][3]);

            uint32_t Vh[8][2], Vl[8][2];
            #pragma unroll
            for (int np = 0; np < 4; np++) {
                uint32_t x0, x1, x2, x3;
                uint32_t off = sb + 64*LDK*2 + (uint32_t)((kt*16 + v_row)*LDK + np*16 + v_col) * 2;
                ldsm_x4_t(x0, x1, x2, x3, off);
                Vh[np*2+0][0] = x0; Vh[np*2+0][1] = x1;
                Vh[np*2+1][0] = x2; Vh[np*2+1][1] = x3;
                ldsm_x4_t(x0, x1, x2, x3, off + 64*LDK*2);
                Vl[np*2+0][0] = x0; Vl[np*2+0][1] = x1;
                Vl[np*2+1][0] = x2; Vl[np*2+1][1] = x3;
            }
            #pragma unroll
            for (int nt = 0; nt < 8; nt++) {
                mma_f16(O[nt], Ah, Vh[nt]);
                mma_f16(O[nt], Ah, Vl[nt]);
            }
        }

        // ---- store prefetched tile into the other stage ----
        if (more) {
            __half* nx = dsm + (cur ^ 1) * A_STAGE_EL;
            cvt_store_h(pk0, pk1, nx + row4*LDK + c04);
            cvt_store_h(pk2, pk3, nx + row4*LDK + c04 + 8);
            split_store_h(pv0, pv1, nx + (64+row4)*LDK + c04,     nx + (128+row4)*LDK + c04);
            split_store_h(pv2, pv3, nx + (64+row4)*LDK + c04 + 8, nx + (128+row4)*LDK + c04 + 8);
        }
        __syncthreads();
    }

    // ---- finalize ----
    float inv0 = 1.0f / l_i[0];
    float inv1 = 1.0f / l_i[1];
    float* orow0 = g_attn + ((size_t)bh * S_LEN + q0 + warp*16 + r0) * DKH + c2;
    float* orow1 = orow0 + 8 * DKH;
    #pragma unroll
    for (int nt = 0; nt < 8; nt++) {
        *(float2*)(orow0 + nt*8) = make_float2(O[nt][0] * inv0, O[nt][1] * inv0);
        *(float2*)(orow1 + nt*8) = make_float2(O[nt][2] * inv1, O[nt][3] * inv1);
    }
}

extern "C" void kernel_launch(void* const* d_in, const int* in_sizes, int n_in,
                              void* d_out, int out_size)
{
    const float* query = (const float*)d_in[0];
    const float* key_  = (const float*)d_in[1];
    const float* value = (const float*)d_in[2];
    const int*   mask  = (const int*)d_in[3];
    const float* Wq = (const float*)d_in[4];
    const float* bq = (const float*)d_in[5];
    const float* Wk = (const float*)d_in[6];
    const float* bk = (const float*)d_in[7];
    const float* Wv = (const float*)d_in[8];
    const float* bv = (const float*)d_in[9];
    const float* Wo = (const float*)d_in[10];
    const float* bo = (const float*)d_in[11];
    float* out = (float*)d_out;

    cudaFuncSetAttribute(attn_kernel, cudaFuncAttributeMaxDynamicSharedMemorySize,
                         2 * A_STAGE_B);

    dim3 g1(DM / 128, (BB * S_LEN) / 128, 3);
    qkv_proj_kernel<<<g1, 256>>>(query, key_, value, Wq, bq, Wk, bk, Wv, bv);

    dim3 g2(S_LEN / 128, BB * NH);
    attn_kernel<<<g2, 256, 2 * A_STAGE_B>>>(mask);

    dim3 g3(DM / 128, (BB * S_LEN) / 128);
    out_proj_kernel<<<g3, 256>>>(Wo, bo, out);
}

// round 10
// speedup vs baseline: 2.9655x; 1.0978x over previous
#include <cuda_runtime.h>
#include <cuda_fp16.h>
#include <cstdint>

#define S_LEN 2048
#define DM    1024
#define NH    16
#define DKH   64
#define BB    2

// scratch: [B,H,S,DK] layouts
__device__ float g_q[BB*NH*S_LEN*DKH];
__device__ float g_k[BB*NH*S_LEN*DKH];
__device__ float g_v[BB*NH*S_LEN*DKH];
__device__ float g_attn[BB*NH*S_LEN*DKH];

// ---------------------------------------------------------------------------
// MMA helpers (warp-level, fp16 in / f32 out)
// ---------------------------------------------------------------------------
__device__ __forceinline__ void ldsm_x4(uint32_t& r0, uint32_t& r1, uint32_t& r2, uint32_t& r3,
                                        uint32_t addr) {
    asm volatile("ldmatrix.sync.aligned.m8n8.x4.shared.b16 {%0,%1,%2,%3}, [%4];"
                 : "=r"(r0), "=r"(r1), "=r"(r2), "=r"(r3) : "r"(addr));
}

__device__ __forceinline__ void ldsm_x4_t(uint32_t& r0, uint32_t& r1, uint32_t& r2, uint32_t& r3,
                                          uint32_t addr) {
    asm volatile("ldmatrix.sync.aligned.m8n8.x4.trans.shared.b16 {%0,%1,%2,%3}, [%4];"
                 : "=r"(r0), "=r"(r1), "=r"(r2), "=r"(r3) : "r"(addr));
}

__device__ __forceinline__ void mma_f16(float* c, const uint32_t* a, const uint32_t* b) {
    asm volatile(
        "mma.sync.aligned.m16n8k16.row.col.f32.f16.f16.f32 "
        "{%0,%1,%2,%3}, {%4,%5,%6,%7}, {%8,%9}, {%0,%1,%2,%3};"
        : "+f"(c[0]), "+f"(c[1]), "+f"(c[2]), "+f"(c[3])
        : "r"(a[0]), "r"(a[1]), "r"(a[2]), "r"(a[3]), "r"(b[0]), "r"(b[1]));
}

// split 8 floats into fp16 hi/lo and store 16B each
__device__ __forceinline__ void split_store_h(float4 u0, float4 u1,
                                              __half* dst_hi, __half* dst_lo) {
    float x[8] = {u0.x, u0.y, u0.z, u0.w, u1.x, u1.y, u1.z, u1.w};
    __half2 h[4], l[4];
    #pragma unroll
    for (int i = 0; i < 4; i++) {
        float a = x[2*i], b = x[2*i+1];
        __half ha = __float2half_rn(a);
        __half hb = __float2half_rn(b);
        __half la = __float2half_rn(a - __half2float(ha));
        __half lb = __float2half_rn(b - __half2float(hb));
        h[i] = __halves2half2(ha, hb);
        l[i] = __halves2half2(la, lb);
    }
    *(uint4*)dst_hi = *(uint4*)h;
    *(uint4*)dst_lo = *(uint4*)l;
}

// convert 8 floats to single fp16, store 16B
__device__ __forceinline__ void cvt_store_h(float4 u0, float4 u1, __half* dst) {
    __half2 h[4];
    h[0] = __floats2half2_rn(u0.x, u0.y);
    h[1] = __floats2half2_rn(u0.z, u0.w);
    h[2] = __floats2half2_rn(u1.x, u1.y);
    h[3] = __floats2half2_rn(u1.z, u1.w);
    *(uint4*)dst = *(uint4*)h;
}

__device__ __forceinline__ uint32_t pack_h(float a, float b) {
    __half2 t = __floats2half2_rn(a, b);
    return *(uint32_t*)&t;
}

// smem layout constants for the GEMM kernels (2-term: A single, B hi/lo)
#define LDAB 24                 // fp16 per row (16 data + 8 pad)
#define T_A    0
#define T_B_HI (128*LDAB)
#define T_B_LO (2*128*LDAB)
#define G_STAGE_EL (3*128*LDAB)     // elements per stage = 9216
#define G_STAGE_B  (G_STAGE_EL*2)   // bytes per stage = 18432

// ---------------------------------------------------------------------------
// QKV projection: double-buffered 2-term fp16 GEMM (A single, B split hi/lo).
// ---------------------------------------------------------------------------
__global__ __launch_bounds__(256, 2) void qkv_proj_kernel(
    const float* __restrict__ xq, const float* __restrict__ xk, const float* __restrict__ xv,
    const float* __restrict__ Wq, const float* __restrict__ bq,
    const float* __restrict__ Wk, const float* __restrict__ bk,
    const float* __restrict__ Wv, const float* __restrict__ bv)
{
    int z = blockIdx.z;
    const float* X    = (z == 0) ? xq : (z == 1) ? xk : xv;
    const float* W    = (z == 0) ? Wq : (z == 1) ? Wk : Wv;
    const float* bias = (z == 0) ? bq : (z == 1) ? bk : bv;
    float* out        = (z == 0) ? g_q : (z == 1) ? g_k : g_v;

    __shared__ __align__(16) __half sm[2*G_STAGE_EL];   // 36 KB

    int tid  = threadIdx.x;
    int lane = tid & 31;
    int wid  = tid >> 5;
    int wm   = wid & 1;
    int wn   = wid >> 1;
    int m0 = blockIdx.y * 128;
    int n0 = blockIdx.x * 128;

    int grow = tid >> 1;
    int gk8  = (tid & 1) * 8;
    const float* Abase = X + (size_t)(m0 + grow) * DM + gk8;
    const float* Bbase = W + (size_t)(n0 + grow) * DM + gk8;
    __half* sa    = sm + T_A    + grow * LDAB + gk8;
    __half* sb_hi = sm + T_B_HI + grow * LDAB + gk8;
    __half* sb_lo = sm + T_B_LO + grow * LDAB + gk8;

    uint32_t smem_u32 = (uint32_t)__cvta_generic_to_shared(sm);
    int a_row = lane & 15, a_kh = (lane >> 4) * 8;
    uint32_t adA[4];
    #pragma unroll
    for (int mt = 0; mt < 4; mt++) {
        int r = wm * 64 + mt * 16 + a_row;
        adA[mt] = smem_u32 + (uint32_t)(T_A + r * LDAB + a_kh) * 2;
    }
    int b_nrow = ((lane >> 4) & 1) * 8 + (lane & 7);
    int b_k    = ((lane >> 3) & 1) * 8;
    uint32_t adB[2], adBlo[2];
    #pragma unroll
    for (int p = 0; p < 2; p++) {
        int r = wn * 32 + p * 16 + b_nrow;
        adB[p]   = smem_u32 + (uint32_t)(T_B_HI + r * LDAB + b_k) * 2;
        adBlo[p] = smem_u32 + (uint32_t)(T_B_LO + r * LDAB + b_k) * 2;
    }

    float C[4][4][4] = {};

    float4 a0 = *(const float4*)(Abase + 0);
    float4 a1 = *(const float4*)(Abase + 4);
    float4 b0 = *(const float4*)(Bbase + 0);
    float4 b1 = *(const float4*)(Bbase + 4);

    cvt_store_h(a0, a1, sa);
    split_store_h(b0, b1, sb_hi, sb_lo);
    __syncthreads();

    uint32_t curB = 0;
    int      curE = 0;

    for (int k0 = 0; k0 < DM; k0 += 16) {
        bool more = (k0 + 16) < DM;
        if (more) {
            a0 = *(const float4*)(Abase + k0 + 16);
            a1 = *(const float4*)(Abase + k0 + 20);
            b0 = *(const float4*)(Bbase + k0 + 16);
            b1 = *(const float4*)(Bbase + k0 + 20);
        }

        uint32_t A[4][4], Bh[4][2], Bl[4][2];
        #pragma unroll
        for (int mt = 0; mt < 4; mt++)
            ldsm_x4(A[mt][0], A[mt][1], A[mt][2], A[mt][3], adA[mt] + curB);
        #pragma unroll
        for (int p = 0; p < 2; p++) {
            uint32_t r0, r1, r2, r3;
            ldsm_x4(r0, r1, r2, r3, adB[p] + curB);
            Bh[p*2+0][0] = r0; Bh[p*2+0][1] = r1;
            Bh[p*2+1][0] = r2; Bh[p*2+1][1] = r3;
            ldsm_x4(r0, r1, r2, r3, adBlo[p] + curB);
            Bl[p*2+0][0] = r0; Bl[p*2+0][1] = r1;
            Bl[p*2+1][0] = r2; Bl[p*2+1][1] = r3;
        }
        #pragma unroll
        for (int mt = 0; mt < 4; mt++)
            #pragma unroll
            for (int nt = 0; nt < 4; nt++) {
                mma_f16(C[mt][nt], A[mt], Bh[nt]);
                mma_f16(C[mt][nt], A[mt], Bl[nt]);
            }

        if (more) {
            int nx = curE ^ G_STAGE_EL;
            cvt_store_h(a0, a1, sa + nx);
            split_store_h(b0, b1, sb_hi + nx, sb_lo + nx);
        }
        __syncthreads();
        curB ^= G_STAGE_B;
        curE ^= G_STAGE_EL;
    }

    int crow = lane >> 2;
    int ccol = (lane & 3) * 2;
    #pragma unroll
    for (int nt = 0; nt < 4; nt++) {
        int n = n0 + wn * 32 + nt * 8 + ccol;
        int h = n >> 6, dk = n & 63;
        float bi0 = bias[n], bi1 = bias[n + 1];
        #pragma unroll
        for (int mt = 0; mt < 4; mt++) {
            #pragma unroll
            for (int half = 0; half < 2; half++) {
                int m = m0 + wm * 64 + mt * 16 + crow + half * 8;
                int b_ = m >> 11, s = m & 2047;
                float* op = out + (((size_t)(b_ * NH + h)) * S_LEN + s) * DKH + dk;
                float2 r = make_float2(C[mt][nt][half*2+0] + bi0, C[mt][nt][half*2+1] + bi1);
                *(float2*)op = r;
            }
        }
    }
}

// ---------------------------------------------------------------------------
// Output projection: same 2-term structure, head-gathered A.
// ---------------------------------------------------------------------------
__global__ __launch_bounds__(256, 2) void out_proj_kernel(
    const float* __restrict__ Wo, const float* __restrict__ bo, float* __restrict__ out)
{
    __shared__ __align__(16) __half sm[2*G_STAGE_EL];

    int tid  = threadIdx.x;
    int lane = tid & 31;
    int wid  = tid >> 5;
    int wm   = wid & 1;
    int wn   = wid >> 1;
    int m0 = blockIdx.y * 128;
    int n0 = blockIdx.x * 128;

    int grow = tid >> 1;
    int gk8  = (tid & 1) * 8;
    int m  = m0 + grow;
    int b_ = m >> 11, ss = m & 2047;
    const float* arow = g_attn + ((size_t)b_ * NH) * S_LEN * DKH + (size_t)ss * DKH;
    const float* Bbase = Wo + (size_t)(n0 + grow) * DM + gk8;
    __half* sa    = sm + T_A    + grow * LDAB + gk8;
    __half* sb_hi = sm + T_B_HI + grow * LDAB + gk8;
    __half* sb_lo = sm + T_B_LO + grow * LDAB + gk8;

    auto lda = [&](int k) -> float4 {
        return *(const float4*)(arow + (size_t)(k >> 6) * (S_LEN * DKH) + (k & 63));
    };

    uint32_t smem_u32 = (uint32_t)__cvta_generic_to_shared(sm);
    int a_row = lane & 15, a_kh = (lane >> 4) * 8;
    uint32_t adA[4];
    #pragma unroll
    for (int mt = 0; mt < 4; mt++) {
        int r = wm * 64 + mt * 16 + a_row;
        adA[mt] = smem_u32 + (uint32_t)(T_A + r * LDAB + a_kh) * 2;
    }
    int b_nrow = ((lane >> 4) & 1) * 8 + (lane & 7);
    int b_k    = ((lane >> 3) & 1) * 8;
    uint32_t adB[2], adBlo[2];
    #pragma unroll
    for (int p = 0; p < 2; p++) {
        int r = wn * 32 + p * 16 + b_nrow;
        adB[p]   = smem_u32 + (uint32_t)(T_B_HI + r * LDAB + b_k) * 2;
        adBlo[p] = smem_u32 + (uint32_t)(T_B_LO + r * LDAB + b_k) * 2;
    }

    float C[4][4][4] = {};

    float4 a0 = lda(gk8);
    float4 a1 = lda(gk8 + 4);
    float4 b0 = *(const float4*)(Bbase + 0);
    float4 b1 = *(const float4*)(Bbase + 4);

    cvt_store_h(a0, a1, sa);
    split_store_h(b0, b1, sb_hi, sb_lo);
    __syncthreads();

    uint32_t curB = 0;
    int      curE = 0;

    for (int k0 = 0; k0 < DM; k0 += 16) {
        bool more = (k0 + 16) < DM;
        if (more) {
            a0 = lda(k0 + 16 + gk8);
            a1 = lda(k0 + 16 + gk8 + 4);
            b0 = *(const float4*)(Bbase + k0 + 16);
            b1 = *(const float4*)(Bbase + k0 + 20);
        }

        uint32_t A[4][4], Bh[4][2], Bl[4][2];
        #pragma unroll
        for (int mt = 0; mt < 4; mt++)
            ldsm_x4(A[mt][0], A[mt][1], A[mt][2], A[mt][3], adA[mt] + curB);
        #pragma unroll
        for (int p = 0; p < 2; p++) {
            uint32_t r0, r1, r2, r3;
            ldsm_x4(r0, r1, r2, r3, adB[p] + curB);
            Bh[p*2+0][0] = r0; Bh[p*2+0][1] = r1;
            Bh[p*2+1][0] = r2; Bh[p*2+1][1] = r3;
            ldsm_x4(r0, r1, r2, r3, adBlo[p] + curB);
            Bl[p*2+0][0] = r0; Bl[p*2+0][1] = r1;
            Bl[p*2+1][0] = r2; Bl[p*2+1][1] = r3;
        }
        #pragma unroll
        for (int mt = 0; mt < 4; mt++)
            #pragma unroll
            for (int nt = 0; nt < 4; nt++) {
                mma_f16(C[mt][nt], A[mt], Bh[nt]);
                mma_f16(C[mt][nt], A[mt], Bl[nt]);
            }

        if (more) {
            int nx = curE ^ G_STAGE_EL;
            cvt_store_h(a0, a1, sa + nx);
            split_store_h(b0, b1, sb_hi + nx, sb_lo + nx);
        }
        __syncthreads();
        curB ^= G_STAGE_B;
        curE ^= G_STAGE_EL;
    }

    int crow = lane >> 2;
    int ccol = (lane & 3) * 2;
    #pragma unroll
    for (int nt = 0; nt < 4; nt++) {
        int n = n0 + wn * 32 + nt * 8 + ccol;
        float bi0 = bo[n], bi1 = bo[n + 1];
        #pragma unroll
        for (int mt = 0; mt < 4; mt++) {
            #pragma unroll
            for (int half = 0; half < 2; half++) {
                int mr = m0 + wm * 64 + mt * 16 + crow + half * 8;
                float2 r = make_float2(C[mt][nt][half*2+0] + bi0, C[mt][nt][half*2+1] + bi1);
                *(float2*)(out + (size_t)mr * DM + n) = r;
            }
        }
    }
}

// ---------------------------------------------------------------------------
// Flash attention (unchanged from R9): QK = Qh*Kh [1 MMA], PV = P*(Vh+Vl) [2 MMA].
// CTA: 128 q rows x one (b,h); 8 warps x 16 q rows; kv tiles of 64, 2-stage.
// Stage layout (rows of LDK): K single [0-63], V hi [64-127], V lo [128-191].
// ---------------------------------------------------------------------------
#define LDK 72
#define A_STAGE_EL (192*LDK)        // elements per stage = 13824
#define A_STAGE_B  (A_STAGE_EL*2)   // 27648 bytes

extern __shared__ __half dsm[];

__global__ __launch_bounds__(256) void attn_kernel(const int* __restrict__ mask)
{
    const float MSCALE = 0.125f * 1.44269504f;   // (1/8) * log2(e)
    const float MNEG   = -1.442695e9f;           // -1e9 * log2(e)

    int tid  = threadIdx.x;
    int lane = tid & 31;
    int warp = tid >> 5;
    int bh = blockIdx.y;
    int b  = bh >> 4;
    int q0 = blockIdx.x * 128;

    const float* Qg = g_q + (size_t)bh * S_LEN * DKH;
    const float* Kg = g_k + (size_t)bh * S_LEN * DKH;
    const float* Vg = g_v + (size_t)bh * S_LEN * DKH;

    uint32_t base = (uint32_t)__cvta_generic_to_shared(dsm);

    // ---- stage Q (single fp16) into stage0 rows 0-127 ----
    {
        int row = tid >> 1;
        int c0 = (tid & 1) * 32;
        const float* src = Qg + (size_t)(q0 + row) * DKH + c0;
        #pragma unroll
        for (int c = 0; c < 32; c += 8) {
            float4 u0 = *(const float4*)(src + c);
            float4 u1 = *(const float4*)(src + c + 4);
            cvt_store_h(u0, u1, dsm + row*LDK + c0 + c);
        }
    }
    __syncthreads();

    // ---- Q A-fragments (resident all kernel) ----
    uint32_t Qh[4][4];
    {
        int a_row = lane & 15, a_kh = (lane >> 4) * 8;
        #pragma unroll
        for (int kt = 0; kt < 4; kt++) {
            uint32_t off = (uint32_t)((warp*16 + a_row)*LDK + kt*16 + a_kh) * 2;
            ldsm_x4(Qh[kt][0], Qh[kt][1], Qh[kt][2], Qh[kt][3], base + off);
        }
    }
    __syncthreads();   // done reading Q staging before overwriting stage0

    // ---- stage kv tile 0 into stage0 ----
    int row4 = tid >> 2;           // 0..63
    int c04  = (tid & 3) * 16;     // 0,16,32,48
    {
        const float* ks = Kg + (size_t)row4 * DKH + c04;
        const float* vs = Vg + (size_t)row4 * DKH + c04;
        float4 k0_ = *(const float4*)(ks + 0), k1_ = *(const float4*)(ks + 4);
        float4 k2_ = *(const float4*)(ks + 8), k3_ = *(const float4*)(ks + 12);
        cvt_store_h(k0_, k1_, dsm + row4*LDK + c04);
        cvt_store_h(k2_, k3_, dsm + row4*LDK + c04 + 8);
        float4 w0 = *(const float4*)(vs + 0), w1 = *(const float4*)(vs + 4);
        float4 w2 = *(const float4*)(vs + 8), w3 = *(const float4*)(vs + 12);
        split_store_h(w0, w1, dsm + (64+row4)*LDK + c04,     dsm + (128+row4)*LDK + c04);
        split_store_h(w2, w3, dsm + (64+row4)*LDK + c04 + 8, dsm + (128+row4)*LDK + c04 + 8);
    }
    __syncthreads();

    float m_i[2] = {-1e30f, -1e30f};
    float l_i[2] = {0.f, 0.f};
    float O[8][4] = {};

    int r0 = lane >> 2;
    int c2 = (lane & 3) * 2;
    int b_nrow = ((lane >> 4) & 1) * 8 + (lane & 7);
    int b_k    = ((lane >> 3) & 1) * 8;
    int v_row  = ((lane >> 3) & 1) * 8 + (lane & 7);
    int v_col  = (lane >> 4) * 8;

    const float* ksp = Kg + (size_t)row4 * DKH + c04;
    const float* vsp = Vg + (size_t)row4 * DKH + c04;

    for (int it = 0; it < S_LEN/64; it++) {
        int cur = it & 1;
        uint32_t sb = base + (uint32_t)cur * A_STAGE_B;
        bool more = it + 1 < S_LEN/64;

        // ---- prefetch next kv tile into registers ----
        float4 pk0, pk1, pk2, pk3, pv0, pv1, pv2, pv3;
        if (more) {
            const float* ks = ksp + (size_t)(it+1) * 64 * DKH;
            const float* vs = vsp + (size_t)(it+1) * 64 * DKH;
            pk0 = *(const float4*)(ks + 0);  pk1 = *(const float4*)(ks + 4);
            pk2 = *(const float4*)(ks + 8);  pk3 = *(const float4*)(ks + 12);
            pv0 = *(const float4*)(vs + 0);  pv1 = *(const float4*)(vs + 4);
            pv2 = *(const float4*)(vs + 8);  pv3 = *(const float4*)(vs + 12);
        }

        // ---- mask loads issued early (hidden behind QK MMAs) ----
        int k0 = it * 64;
        const int* mrow0 = mask + ((size_t)b * S_LEN + q0 + warp*16 + r0) * S_LEN + k0 + c2;
        const int* mrow1 = mrow0 + 8 * S_LEN;
        int2 mreg0[8], mreg1[8];
        #pragma unroll
        for (int nt = 0; nt < 8; nt++) {
            mreg0[nt] = *(const int2*)(mrow0 + nt*8);
            mreg1[nt] = *(const int2*)(mrow1 + nt*8);
        }

        // ---- S = Q K^T (single-term fp16) ----
        float S[8][4] = {};
        #pragma unroll
        for (int kt = 0; kt < 4; kt++) {
            uint32_t Bh[8][2];
            #pragma unroll
            for (int np = 0; np < 4; np++) {
                uint32_t x0, x1, x2, x3;
                uint32_t off = sb + (uint32_t)((np*16 + b_nrow)*LDK + kt*16 + b_k) * 2;
                ldsm_x4(x0, x1, x2, x3, off);
                Bh[np*2+0][0] = x0; Bh[np*2+0][1] = x1;
                Bh[np*2+1][0] = x2; Bh[np*2+1][1] = x3;
            }
            #pragma unroll
            for (int nt = 0; nt < 8; nt++)
                mma_f16(S[nt], Qh[kt], Bh[nt]);
        }

        // ---- mask + scale (log2 domain) ----
        #pragma unroll
        for (int nt = 0; nt < 8; nt++) {
            S[nt][0] = mreg0[nt].x ? S[nt][0] * MSCALE : MNEG;
            S[nt][1] = mreg0[nt].y ? S[nt][1] * MSCALE : MNEG;
            S[nt][2] = mreg1[nt].x ? S[nt][2] * MSCALE : MNEG;
            S[nt][3] = mreg1[nt].y ? S[nt][3] * MSCALE : MNEG;
        }

        // ---- online softmax (base-2) ----
        #pragma unroll
        for (int h = 0; h < 2; h++) {
            float mx = -1e30f;
            #pragma unroll
            for (int nt = 0; nt < 8; nt++)
                mx = fmaxf(mx, fmaxf(S[nt][2*h], S[nt][2*h+1]));
            mx = fmaxf(mx, __shfl_xor_sync(0xffffffffu, mx, 1));
            mx = fmaxf(mx, __shfl_xor_sync(0xffffffffu, mx, 2));
            float mnew  = fmaxf(m_i[h], mx);
            float alpha = exp2f(m_i[h] - mnew);
            m_i[h] = mnew;
            float ls = 0.f;
            #pragma unroll
            for (int nt = 0; nt < 8; nt++) {
                S[nt][2*h]   = exp2f(S[nt][2*h]   - mnew);
                S[nt][2*h+1] = exp2f(S[nt][2*h+1] - mnew);
                ls += S[nt][2*h] + S[nt][2*h+1];
            }
            ls += __shfl_xor_sync(0xffffffffu, ls, 1);
            ls += __shfl_xor_sync(0xffffffffu, ls, 2);
            l_i[h] = l_i[h] * alpha + ls;
            #pragma unroll
            for (int nt = 0; nt < 8; nt++) { O[nt][2*h] *= alpha; O[nt][2*h+1] *= alpha; }
        }

        // ---- O += P V (P single fp16, V hi/lo) ----
        #pragma unroll
        for (int kt = 0; kt < 4; kt++) {
            uint32_t Ah[4];
            Ah[0] = pack_h(S[2*kt+0][0], S[2*kt+0][1]);
            Ah[1] = pack_h(S[2*kt+0][2], S[2*kt+0][3]);
            Ah[2] = pack_h(S[2*kt+1][0], S[2*kt+1][1]);
            Ah[3] = pack_h(S[2*kt+1][2], S[2*kt+1][3]);

            uint32_t Vh[8][2], Vl[8][2];
            #pragma unroll
            for (int np = 0; np < 4; np++) {
                uint32_t x0, x1, x2, x3;
                uint32_t off = sb + 64*LDK*2 + (uint32_t)((kt*16 + v_row)*LDK + np*16 + v_col) * 2;
                ldsm_x4_t(x0, x1, x2, x3, off);
                Vh[np*2+0][0] = x0; Vh[np*2+0][1] = x1;
                Vh[np*2+1][0] = x2; Vh[np*2+1][1] = x3;
                ldsm_x4_t(x0, x1, x2, x3, off + 64*LDK*2);
                Vl[np*2+0][0] = x0; Vl[np*2+0][1] = x1;
                Vl[np*2+1][0] = x2; Vl[np*2+1][1] = x3;
            }
            #pragma unroll
            for (int nt = 0; nt < 8; nt++) {
                mma_f16(O[nt], Ah, Vh[nt]);
                mma_f16(O[nt], Ah, Vl[nt]);
            }
        }

        // ---- store prefetched tile into the other stage ----
        if (more) {
            __half* nx = dsm + (cur ^ 1) * A_STAGE_EL;
            cvt_store_h(pk0, pk1, nx + row4*LDK + c04);
            cvt_store_h(pk2, pk3, nx + row4*LDK + c04 + 8);
            split_store_h(pv0, pv1, nx + (64+row4)*LDK + c04,     nx + (128+row4)*LDK + c04);
            split_store_h(pv2, pv3, nx + (64+row4)*LDK + c04 + 8, nx + (128+row4)*LDK + c04 + 8);
        }
        __syncthreads();
    }

    // ---- finalize ----
    float inv0 = 1.0f / l_i[0];
    float inv1 = 1.0f / l_i[1];
    float* orow0 = g_attn + ((size_t)bh * S_LEN + q0 + warp*16 + r0) * DKH + c2;
    float* orow1 = orow0 + 8 * DKH;
    #pragma unroll
    for (int nt = 0; nt < 8; nt++) {
        *(float2*)(orow0 + nt*8) = make_float2(O[nt][0] * inv0, O[nt][1] * inv0);
        *(float2*)(orow1 + nt*8) = make_float2(O[nt][2] * inv1, O[nt][3] * inv1);
    }
}

extern "C" void kernel_launch(void* const* d_in, const int* in_sizes, int n_in,
                              void* d_out, int out_size)
{
    const float* query = (const float*)d_in[0];
    const float* key_  = (const float*)d_in[1];
    const float* value = (const float*)d_in[2];
    const int*   mask  = (const int*)d_in[3];
    const float* Wq = (const float*)d_in[4];
    const float* bq = (const float*)d_in[5];
    const float* Wk = (const float*)d_in[6];
    const float* bk = (const float*)d_in[7];
    const float* Wv = (const float*)d_in[8];
    const float* bv = (const float*)d_in[9];
    const float* Wo = (const float*)d_in[10];
    const float* bo = (const float*)d_in[11];
    float* out = (float*)d_out;

    cudaFuncSetAttribute(attn_kernel, cudaFuncAttributeMaxDynamicSharedMemorySize,
                         2 * A_STAGE_B);

    dim3 g1(DM / 128, (BB * S_LEN) / 128, 3);
    qkv_proj_kernel<<<g1, 256>>>(query, key_, value, Wq, bq, Wk, bk, Wv, bv);

    dim3 g2(S_LEN / 128, BB * NH);
    attn_kernel<<<g2, 256, 2 * A_STAGE_B>>>(mask);

    dim3 g3(DM / 128, (BB * S_LEN) / 128);
    out_proj_kernel<<<g3, 256>>>(Wo, bo, out);
}